// round 9
// baseline (speedup 1.0000x reference)
#include <cuda_runtime.h>
#include <cuda_bf16.h>
#include <math.h>
#include <stdint.h>

#define B_   4
#define N_   4096
#define DIMM 1024
#define HEADS 16
#define HD   64
#define ROWS (B_*N_)          // 16384
#define NCH  64               // chunks per (b,h)
#define NBH  (B_*HEADS)       // 64
#define NGC  (NBH*NCH)        // 4096 chunk-blocks

// ---------------- scratch (device globals: allocation-free) ----------------
__device__ float g_qkv[(size_t)ROWS * 3 * DIMM];        // qkv fp32
__device__ float g_qf [(size_t)B_*HEADS*N_*HD];
__device__ float g_kf [(size_t)B_*HEADS*N_*HD];
__device__ float g_vf [(size_t)B_*HEADS*N_*HD];
__device__ float g_kvc[(size_t)NGC * HD * HD];          // per-chunk KV states 64MB
__device__ float g_ksc[(size_t)NGC * HD];               // per-chunk ks sums
__device__ __nv_bfloat16 g_xh [(size_t)ROWS * DIMM];    // x split
__device__ __nv_bfloat16 g_xl [(size_t)ROWS * DIMM];
__device__ __nv_bfloat16 g_ah [(size_t)ROWS * DIMM];    // attn split (pass2 out)
__device__ __nv_bfloat16 g_al [(size_t)ROWS * DIMM];
__device__ __nv_bfloat16 g_wqh[(size_t)3 * DIMM * DIMM]; // wqkv^T split [N][K]
__device__ __nv_bfloat16 g_wql[(size_t)3 * DIMM * DIMM];
__device__ __nv_bfloat16 g_woh[(size_t)DIMM * DIMM];     // wout^T split
__device__ __nv_bfloat16 g_wol[(size_t)DIMM * DIMM];

// ---------------- helpers ----------------------------------------------------
__device__ __forceinline__ uint32_t smem_u32(const void* p) {
    uint32_t a;
    asm("{ .reg .u64 t; cvta.to.shared.u64 t, %1; cvt.u32.u64 %0, t; }"
        : "=r"(a) : "l"(p));
    return a;
}
__device__ __forceinline__ void cp16(uint32_t s, const void* g) {
    asm volatile("cp.async.cg.shared.global [%0], [%1], 16;" :: "r"(s), "l"(g));
}
#define CP_COMMIT() asm volatile("cp.async.commit_group;" ::: "memory")
#define CP_WAIT(n)  asm volatile("cp.async.wait_group %0;" :: "n"(n) : "memory")
#define LDSM4(r0, r1, r2, r3, addr) asm volatile( \
    "ldmatrix.sync.aligned.m8n8.x4.shared.b16 {%0,%1,%2,%3}, [%4];" \
    : "=r"(r0), "=r"(r1), "=r"(r2), "=r"(r3) : "r"(addr))
__device__ __forceinline__ void mma16816(float* c, const uint32_t* a,
                                         const uint32_t* b) {
    asm volatile(
        "mma.sync.aligned.m16n8k16.row.col.f32.bf16.bf16.f32 "
        "{%0,%1,%2,%3}, {%4,%5,%6,%7}, {%8,%9}, {%0,%1,%2,%3};"
        : "+f"(c[0]), "+f"(c[1]), "+f"(c[2]), "+f"(c[3])
        : "r"(a[0]), "r"(a[1]), "r"(a[2]), "r"(a[3]), "r"(b[0]), "r"(b[1]));
}
__device__ __forceinline__ uint32_t swz(int r, int ck) {
    return (uint32_t)(((r >> 1) << 7) |
                      ((((((r & 1) << 2) | ck)) ^ ((r >> 1) & 7)) << 4));
}

// ---------------- split fp32 -> bf16 hi/lo ----------------------------------
__global__ void split_bf16(const float* __restrict__ in,
                           __nv_bfloat16* __restrict__ hi,
                           __nv_bfloat16* __restrict__ lo, int n4) {
    int i = blockIdx.x * blockDim.x + threadIdx.x;
    if (i >= n4) return;
    float4 v = ((const float4*)in)[i];
    __nv_bfloat16 h0 = __float2bfloat16(v.x), h1 = __float2bfloat16(v.y);
    __nv_bfloat16 h2 = __float2bfloat16(v.z), h3 = __float2bfloat16(v.w);
    __nv_bfloat16 l0 = __float2bfloat16(v.x - __bfloat162float(h0));
    __nv_bfloat16 l1 = __float2bfloat16(v.y - __bfloat162float(h1));
    __nv_bfloat16 l2 = __float2bfloat16(v.z - __bfloat162float(h2));
    __nv_bfloat16 l3 = __float2bfloat16(v.w - __bfloat162float(h3));
    ((ushort4*)hi)[i] = make_ushort4(__bfloat16_as_ushort(h0), __bfloat16_as_ushort(h1),
                                     __bfloat16_as_ushort(h2), __bfloat16_as_ushort(h3));
    ((ushort4*)lo)[i] = make_ushort4(__bfloat16_as_ushort(l0), __bfloat16_as_ushort(l1),
                                     __bfloat16_as_ushort(l2), __bfloat16_as_ushort(l3));
}

// ---------------- transpose + split: w[K][N] -> wt_hi/lo [N][K] --------------
__global__ void transpose_split(const float* __restrict__ w,
                                __nv_bfloat16* __restrict__ th,
                                __nv_bfloat16* __restrict__ tl, int K, int N) {
    __shared__ float t[32][33];
    int tx = threadIdx.x, ty = threadIdx.y;
    int x = blockIdx.x * 32 + tx;
#pragma unroll
    for (int j = 0; j < 32; j += 8) {
        int y = blockIdx.y * 32 + ty + j;
        t[ty + j][tx] = w[(size_t)y * N + x];
    }
    __syncthreads();
#pragma unroll
    for (int j = 0; j < 32; j += 8) {
        int n = blockIdx.x * 32 + ty + j;
        int k = blockIdx.y * 32 + tx;
        float v = t[tx][ty + j];
        __nv_bfloat16 h = __float2bfloat16(v);
        th[(size_t)n * K + k] = h;
        tl[(size_t)n * K + k] = __float2bfloat16(v - __bfloat162float(h));
    }
}

// ---------------- split-bf16 tensor-core GEMM (mma.sync) ---------------------
#define STAGE    32768
#define OFFS_AH  0
#define OFFS_AL  8192
#define OFFS_BH  16384
#define OFFS_BL  24576
#define GEMM_SMEM (2 * STAGE)

__global__ void __launch_bounds__(256, 2) mma_gemm(
    const __nv_bfloat16* __restrict__ Ah, const __nv_bfloat16* __restrict__ Al,
    const __nv_bfloat16* __restrict__ Bh, const __nv_bfloat16* __restrict__ Bl,
    float* __restrict__ C, int M, int N, int K) {
    extern __shared__ char sm[];
    const uint32_t sb = smem_u32(sm);
    const int tid = threadIdx.x;
    const int lane = tid & 31, wid = tid >> 5;
    const int warp_m = wid & 1, warp_n = wid >> 1;
    const int m0 = blockIdx.y * 128, n0 = blockIdx.x * 128;

    const int i0 = tid, i1 = tid + 256;
    const int lr0 = i0 >> 2, lc0 = i0 & 3;
    const int lr1 = i1 >> 2, lc1 = i1 & 3;
    const uint32_t so0 = swz(lr0, lc0), so1 = swz(lr1, lc1);

    uint32_t baseA[4], baseB[2];
#pragma unroll
    for (int mf = 0; mf < 4; mf++)
        baseA[mf] = swz(warp_m * 64 + mf * 16 + (lane & 15), lane >> 4);
#pragma unroll
    for (int p = 0; p < 2; p++)
        baseB[p] = swz(warp_n * 32 + p * 16 + ((lane >> 4) << 3) + (lane & 7),
                       (lane >> 3) & 1);

    float acc[4][4][4];
#pragma unroll
    for (int a = 0; a < 4; a++)
#pragma unroll
        for (int b = 0; b < 4; b++)
#pragma unroll
            for (int c = 0; c < 4; c++) acc[a][b][c] = 0.f;

    const int nIter = K >> 5;
    {
        uint32_t bs = sb;
        size_t a0 = (size_t)(m0 + lr0) * K + lc0 * 8;
        size_t a1 = (size_t)(m0 + lr1) * K + lc1 * 8;
        size_t b0 = (size_t)(n0 + lr0) * K + lc0 * 8;
        size_t b1 = (size_t)(n0 + lr1) * K + lc1 * 8;
        cp16(bs + OFFS_AH + so0, Ah + a0); cp16(bs + OFFS_AH + so1, Ah + a1);
        cp16(bs + OFFS_AL + so0, Al + a0); cp16(bs + OFFS_AL + so1, Al + a1);
        cp16(bs + OFFS_BH + so0, Bh + b0); cp16(bs + OFFS_BH + so1, Bh + b1);
        cp16(bs + OFFS_BL + so0, Bl + b0); cp16(bs + OFFS_BL + so1, Bl + b1);
        CP_COMMIT();
    }

    for (int it = 0; it < nIter; it++) {
        if (it + 1 < nIter) {
            int kk = (it + 1) << 5;
            uint32_t bs = sb + ((it + 1) & 1) * STAGE;
            size_t a0 = (size_t)(m0 + lr0) * K + kk + lc0 * 8;
            size_t a1 = (size_t)(m0 + lr1) * K + kk + lc1 * 8;
            size_t b0 = (size_t)(n0 + lr0) * K + kk + lc0 * 8;
            size_t b1 = (size_t)(n0 + lr1) * K + kk + lc1 * 8;
            cp16(bs + OFFS_AH + so0, Ah + a0); cp16(bs + OFFS_AH + so1, Ah + a1);
            cp16(bs + OFFS_AL + so0, Al + a0); cp16(bs + OFFS_AL + so1, Al + a1);
            cp16(bs + OFFS_BH + so0, Bh + b0); cp16(bs + OFFS_BH + so1, Bh + b1);
            cp16(bs + OFFS_BL + so0, Bl + b0); cp16(bs + OFFS_BL + so1, Bl + b1);
            CP_COMMIT();
            CP_WAIT(1);
        } else {
            CP_WAIT(0);
        }
        __syncthreads();

        const uint32_t ss = sb + (it & 1) * STAGE;
#pragma unroll
        for (int ks = 0; ks < 2; ks++) {
            const uint32_t kx = ks * 32;
            uint32_t bh[4][2], bl[4][2];
#pragma unroll
            for (int p = 0; p < 2; p++) {
                uint32_t r0, r1, r2, r3;
                LDSM4(r0, r1, r2, r3, ss + OFFS_BH + (baseB[p] ^ kx));
                bh[2 * p][0] = r0; bh[2 * p][1] = r1;
                bh[2 * p + 1][0] = r2; bh[2 * p + 1][1] = r3;
                LDSM4(r0, r1, r2, r3, ss + OFFS_BL + (baseB[p] ^ kx));
                bl[2 * p][0] = r0; bl[2 * p][1] = r1;
                bl[2 * p + 1][0] = r2; bl[2 * p + 1][1] = r3;
            }
#pragma unroll
            for (int mf = 0; mf < 4; mf++) {
                uint32_t ah[4], al[4];
                LDSM4(ah[0], ah[1], ah[2], ah[3], ss + OFFS_AH + (baseA[mf] ^ kx));
                LDSM4(al[0], al[1], al[2], al[3], ss + OFFS_AL + (baseA[mf] ^ kx));
#pragma unroll
                for (int nf = 0; nf < 4; nf++) {
                    mma16816(acc[mf][nf], ah, bh[nf]);
                    mma16816(acc[mf][nf], ah, bl[nf]);
                    mma16816(acc[mf][nf], al, bh[nf]);
                }
            }
        }
        __syncthreads();
    }

#pragma unroll
    for (int mf = 0; mf < 4; mf++) {
#pragma unroll
        for (int nf = 0; nf < 4; nf++) {
            int row = m0 + warp_m * 64 + mf * 16 + (lane >> 2);
            int col = n0 + warp_n * 32 + nf * 8 + 2 * (lane & 3);
            *(float2*)(C + (size_t)row * N + col) =
                make_float2(acc[mf][nf][0], acc[mf][nf][1]);
            *(float2*)(C + (size_t)(row + 8) * N + col) =
                make_float2(acc[mf][nf][2], acc[mf][nf][3]);
        }
    }
}

// ---------------- RoPE + ELU feature map + transpose to (B,H,N,D) ----------
__global__ void rope_elu(const float* __restrict__ qkv,
                         float* __restrict__ qf, float* __restrict__ kf,
                         float* __restrict__ vf) {
    int idx = blockIdx.x * blockDim.x + threadIdx.x;
    const int total = B_ * N_ * HEADS * 32;
    if (idx >= total) return;
    const int d2 = idx & 31;
    const int h  = (idx >> 5) & 15;
    const int n  = (idx >> 9) & 4095;
    const int b  = idx >> 21;

    size_t base = (size_t)(b * N_ + n) * (3 * DIMM);
    int c1 = h * 64 + d2;
    float q1 = qkv[base + c1],            q2 = qkv[base + c1 + 32];
    float k1 = qkv[base + 1024 + c1],     k2 = qkv[base + 1024 + c1 + 32];
    float v1 = qkv[base + 2048 + c1],     v2 = qkv[base + 2048 + c1 + 32];

    float inv = powf(10000.f, -(float)d2 * (1.f / 32.f));
    float ang = (float)n * inv;
    float cs = cosf(ang), sn = sinf(ang);
    float qr1 = q1 * cs - q2 * sn, qr2 = q1 * sn + q2 * cs;
    float kr1 = k1 * cs - k2 * sn, kr2 = k1 * sn + k2 * cs;

    const float SC = 0.35355339059327373f;
    float y;
    y = qr1 * SC; float fq1 = (y > 0.f) ? y + 1.f : expf(y);
    y = qr2 * SC; float fq2 = (y > 0.f) ? y + 1.f : expf(y);
    y = kr1 * SC; float fk1 = (y > 0.f) ? y + 1.f : expf(y);
    y = kr2 * SC; float fk2 = (y > 0.f) ? y + 1.f : expf(y);

    size_t ob = ((size_t)(b * HEADS + h) * N_ + n) * HD;
    qf[ob + d2] = fq1;  qf[ob + d2 + 32] = fq2;
    kf[ob + d2] = fk1;  kf[ob + d2 + 32] = fk2;
    vf[ob + d2] = v1;   vf[ob + d2 + 32] = v2;
}

// ---------------- pass1: per-chunk KV_c = K_c^T V_c, ks_c = colsum(K_c) ------
__global__ void __launch_bounds__(256) la_pass1(const float* __restrict__ kf,
                                                const float* __restrict__ vf,
                                                float* __restrict__ kvc,
                                                float* __restrict__ ksc) {
    __shared__ float Ks[4096], Vs[4096];
    const int tid = threadIdx.x;
    const int gc = blockIdx.x;            // bh*64 + c
    const int n0 = (gc & 63) * 64;
    const int bh = gc >> 6;
    const float* kb = kf + (size_t)bh * N_ * HD;
    const float* vb = vf + (size_t)bh * N_ * HD;

    const int li = tid >> 2, lq = (tid & 3) * 16;
#pragma unroll
    for (int t = 0; t < 4; t++) {
        *(float4*)&Ks[li * 64 + lq + t * 4] =
            *(const float4*)(kb + (size_t)(n0 + li) * HD + lq + t * 4);
        *(float4*)&Vs[li * 64 + lq + t * 4] =
            *(const float4*)(vb + (size_t)(n0 + li) * HD + lq + t * 4);
    }
    __syncthreads();

    const int g1 = tid >> 4, g2 = tid & 15;   // d block, m block
    float acc[16];
#pragma unroll
    for (int z = 0; z < 16; z++) acc[z] = 0.f;
    for (int i = 0; i < 64; i++) {
        float4 kk = *(float4*)&Ks[i * 64 + g1 * 4];
        float4 vv = *(float4*)&Vs[i * 64 + g2 * 4];
        float ka[4] = {kk.x, kk.y, kk.z, kk.w};
        float va[4] = {vv.x, vv.y, vv.z, vv.w};
#pragma unroll
        for (int dd = 0; dd < 4; dd++)
#pragma unroll
            for (int mm = 0; mm < 4; mm++)
                acc[dd * 4 + mm] += ka[dd] * va[mm];
    }
    float* kvp = kvc + (size_t)gc * 4096;
#pragma unroll
    for (int dd = 0; dd < 4; dd++)
        *(float4*)(kvp + (g1 * 4 + dd) * 64 + g2 * 4) =
            make_float4(acc[dd * 4 + 0], acc[dd * 4 + 1],
                        acc[dd * 4 + 2], acc[dd * 4 + 3]);
    if (tid < 64) {
        float s = 0.f;
        for (int i = 0; i < 64; i++) s += Ks[i * 64 + tid];
        ksc[(size_t)gc * 64 + tid] = s;
    }
}

// ---------------- prefix: in-place EXCLUSIVE prefix over chunks --------------
__global__ void __launch_bounds__(256) la_prefix(float* __restrict__ kvc,
                                                 float* __restrict__ ksc) {
    const int bh = blockIdx.x;
    const int tid = threadIdx.x;
    float st[16];
#pragma unroll
    for (int z = 0; z < 16; z++) st[z] = 0.f;
    float kst = 0.f;
    for (int c = 0; c < 64; c++) {
        float* p = kvc + ((size_t)(bh * 64 + c)) * 4096;
#pragma unroll
        for (int z = 0; z < 16; z++) {
            float t = p[z * 256 + tid];
            p[z * 256 + tid] = st[z];
            st[z] += t;
        }
        if (tid < 64) {
            float* q = ksc + ((size_t)(bh * 64 + c)) * 64 + tid;
            float t = *q;
            *q = kst;
            kst += t;
        }
    }
}

// ---------------- pass2: intra-chunk output (+ fused bf16 hi/lo split) -------
#define P2_SMEM ((5 * 4096 + 128) * 4)
__global__ void __launch_bounds__(256) la_pass2(
    const float* __restrict__ qf, const float* __restrict__ kf,
    const float* __restrict__ vf, const float* __restrict__ kvc,
    const float* __restrict__ ksc,
    __nv_bfloat16* __restrict__ ah, __nv_bfloat16* __restrict__ al) {
    extern __shared__ float smf[];
    float* QsT = smf;             // [d][i]
    float* KsT = QsT + 4096;      // [d][j]
    float* Vs  = KsT + 4096;      // [j][m]
    float* STs = Vs + 4096;       // [j][i]
    float* KV  = STs + 4096;      // [d][m] (prefix state)
    float* kss = KV + 4096;       // [64]
    float* den = kss + 64;        // [64]

    const int tid = threadIdx.x;
    const int gc = blockIdx.x;
    const int c = gc & 63, bh = gc >> 6;
    const int b = bh >> 4, h = bh & 15;
    const int n0 = c * 64;
    const float* qb = qf + (size_t)bh * N_ * HD;
    const float* kb = kf + (size_t)bh * N_ * HD;
    const float* vb = vf + (size_t)bh * N_ * HD;

    // loads
    {
        const int li = tid >> 2, lq = (tid & 3) * 16;
        const float* qrow = qb + (size_t)(n0 + li) * HD + lq;
        const float* krow = kb + (size_t)(n0 + li) * HD + lq;
        const float* vrow = vb + (size_t)(n0 + li) * HD + lq;
#pragma unroll
        for (int t = 0; t < 4; t++) {
            int d0 = lq + t * 4;
            float4 qv = *(const float4*)(qrow + t * 4);
            QsT[(d0 + 0) * 64 + li] = qv.x;
            QsT[(d0 + 1) * 64 + li] = qv.y;
            QsT[(d0 + 2) * 64 + li] = qv.z;
            QsT[(d0 + 3) * 64 + li] = qv.w;
            float4 kv4 = *(const float4*)(krow + t * 4);
            KsT[(d0 + 0) * 64 + li] = kv4.x;
            KsT[(d0 + 1) * 64 + li] = kv4.y;
            KsT[(d0 + 2) * 64 + li] = kv4.z;
            KsT[(d0 + 3) * 64 + li] = kv4.w;
            *(float4*)&Vs[li * 64 + d0] = *(const float4*)(vrow + t * 4);
        }
        const float* kvp = kvc + (size_t)gc * 4096;
        for (int i = tid; i < 4096; i += 256) KV[i] = kvp[i];
        if (tid < 64) kss[tid] = ksc[(size_t)gc * 64 + tid];
    }
    __syncthreads();

    const int g1 = tid >> 4, g2 = tid & 15;
    // S^T[j][i] masked
    {
        float accS[16];
#pragma unroll
        for (int z = 0; z < 16; z++) accS[z] = 0.f;
        for (int d = 0; d < 64; d++) {
            float4 qv = *(float4*)&QsT[d * 64 + g2 * 4];
            float4 kk = *(float4*)&KsT[d * 64 + g1 * 4];
            float qa[4] = {qv.x, qv.y, qv.z, qv.w};
            float ka[4] = {kk.x, kk.y, kk.z, kk.w};
#pragma unroll
            for (int jj = 0; jj < 4; jj++)
#pragma unroll
                for (int ii = 0; ii < 4; ii++)
                    accS[jj * 4 + ii] += ka[jj] * qa[ii];
        }
#pragma unroll
        for (int jj = 0; jj < 4; jj++)
#pragma unroll
            for (int ii = 0; ii < 4; ii++) {
                int j = g1 * 4 + jj, i = g2 * 4 + ii;
                STs[j * 64 + i] = (j <= i) ? accS[jj * 4 + ii] : 0.f;
            }
    }
    __syncthreads();
    if (tid < 64) {
        int i = tid;
        float s = 0.f;
        for (int d = 0; d < 64; d++) s += QsT[d * 64 + i] * kss[d];
        for (int j = 0; j <= i; j++) s += STs[j * 64 + i];
        den[i] = fmaxf(s, 1e-6f);
    }
    __syncthreads();
    // out[i][m] = (Q.KV_prev + S.V)/den, fused bf16 hi/lo split
    {
        float acc[16];
#pragma unroll
        for (int z = 0; z < 16; z++) acc[z] = 0.f;
        for (int d = 0; d < 64; d++) {
            float4 qv = *(float4*)&QsT[d * 64 + g1 * 4];
            float4 kvv = *(float4*)&KV[d * 64 + g2 * 4];
            float qa[4] = {qv.x, qv.y, qv.z, qv.w};
            float ka[4] = {kvv.x, kvv.y, kvv.z, kvv.w};
#pragma unroll
            for (int ii = 0; ii < 4; ii++)
#pragma unroll
                for (int mm = 0; mm < 4; mm++)
                    acc[ii * 4 + mm] += qa[ii] * ka[mm];
        }
        for (int j = 0; j < 64; j++) {
            float4 sv = *(float4*)&STs[j * 64 + g1 * 4];
            float4 vv = *(float4*)&Vs[j * 64 + g2 * 4];
            float sa[4] = {sv.x, sv.y, sv.z, sv.w};
            float va[4] = {vv.x, vv.y, vv.z, vv.w};
#pragma unroll
            for (int ii = 0; ii < 4; ii++)
#pragma unroll
                for (int mm = 0; mm < 4; mm++)
                    acc[ii * 4 + mm] += sa[ii] * va[mm];
        }
#pragma unroll
        for (int ii = 0; ii < 4; ii++) {
            int i = g1 * 4 + ii;
            float inv = 1.f / den[i];
            size_t ro = (size_t)(b * N_ + n0 + i) * DIMM + h * HD + g2 * 4;
            ushort4 uh, ul;
            float v0 = acc[ii * 4 + 0] * inv, v1 = acc[ii * 4 + 1] * inv;
            float v2 = acc[ii * 4 + 2] * inv, v3 = acc[ii * 4 + 3] * inv;
            __nv_bfloat16 h0 = __float2bfloat16(v0), h1 = __float2bfloat16(v1);
            __nv_bfloat16 h2 = __float2bfloat16(v2), h3 = __float2bfloat16(v3);
            uh = make_ushort4(__bfloat16_as_ushort(h0), __bfloat16_as_ushort(h1),
                              __bfloat16_as_ushort(h2), __bfloat16_as_ushort(h3));
            ul = make_ushort4(
                __bfloat16_as_ushort(__float2bfloat16(v0 - __bfloat162float(h0))),
                __bfloat16_as_ushort(__float2bfloat16(v1 - __bfloat162float(h1))),
                __bfloat16_as_ushort(__float2bfloat16(v2 - __bfloat162float(h2))),
                __bfloat16_as_ushort(__float2bfloat16(v3 - __bfloat162float(h3))));
            *(ushort4*)(ah + ro) = uh;
            *(ushort4*)(al + ro) = ul;
        }
    }
}

// ---------------- launch -----------------------------------------------------
extern "C" void kernel_launch(void* const* d_in, const int* in_sizes, int n_in,
                              void* d_out, int out_size) {
    const float* x    = (const float*)d_in[0];
    const float* wqkv = (const float*)d_in[1];
    const float* wout = (const float*)d_in[2];
    float* out = (float*)d_out;

    float *qkv, *qf, *kf, *vf, *kvc, *ksc;
    __nv_bfloat16 *xh, *xl, *ah, *al, *wqh, *wql, *woh, *wol;
    cudaGetSymbolAddress((void**)&qkv, g_qkv);
    cudaGetSymbolAddress((void**)&qf,  g_qf);
    cudaGetSymbolAddress((void**)&kf,  g_kf);
    cudaGetSymbolAddress((void**)&vf,  g_vf);
    cudaGetSymbolAddress((void**)&kvc, g_kvc);
    cudaGetSymbolAddress((void**)&ksc, g_ksc);
    cudaGetSymbolAddress((void**)&xh,  g_xh);
    cudaGetSymbolAddress((void**)&xl,  g_xl);
    cudaGetSymbolAddress((void**)&ah,  g_ah);
    cudaGetSymbolAddress((void**)&al,  g_al);
    cudaGetSymbolAddress((void**)&wqh, g_wqh);
    cudaGetSymbolAddress((void**)&wql, g_wql);
    cudaGetSymbolAddress((void**)&woh, g_woh);
    cudaGetSymbolAddress((void**)&wol, g_wol);

    cudaFuncSetAttribute(mma_gemm, cudaFuncAttributeMaxDynamicSharedMemorySize,
                         GEMM_SMEM);
    cudaFuncSetAttribute(la_pass2, cudaFuncAttributeMaxDynamicSharedMemorySize,
                         P2_SMEM);

    // split x; transpose+split weights
    {
        int n4 = ROWS * DIMM / 4;
        split_bf16<<<(n4 + 255) / 256, 256>>>(x, xh, xl, n4);
        transpose_split<<<dim3(3 * DIMM / 32, DIMM / 32), dim3(32, 8)>>>(
            wqkv, wqh, wql, DIMM, 3 * DIMM);
        transpose_split<<<dim3(DIMM / 32, DIMM / 32), dim3(32, 8)>>>(
            wout, woh, wol, DIMM, DIMM);
    }
    // 1) qkv = x @ w_qkv   (tensor cores)
    mma_gemm<<<dim3(3 * DIMM / 128, ROWS / 128), 256, GEMM_SMEM>>>(
        xh, xl, wqh, wql, qkv, ROWS, 3 * DIMM, DIMM);
    // 2) RoPE + ELU + transpose
    {
        int total = B_ * N_ * HEADS * 32;
        rope_elu<<<(total + 255) / 256, 256>>>(qkv, qf, kf, vf);
    }
    // 3) chunk-parallel linear attention (3 passes; pass2 emits bf16 splits)
    la_pass1<<<NGC, 256>>>(kf, vf, kvc, ksc);
    la_prefix<<<NBH, 256>>>(kvc, ksc);
    la_pass2<<<NGC, 256, P2_SMEM>>>(qf, kf, vf, kvc, ksc, ah, al);
    // 4) out = attn @ w_out (tensor cores)
    mma_gemm<<<dim3(DIMM / 128, ROWS / 128), 256, GEMM_SMEM>>>(
        ah, al, woh, wol, out, ROWS, DIMM, DIMM);
}

// round 10
// speedup vs baseline: 1.2030x; 1.2030x over previous
#include <cuda_runtime.h>
#include <cuda_bf16.h>
#include <math.h>
#include <stdint.h>

#define B_   4
#define N_   4096
#define DIMM 1024
#define HEADS 16
#define HD   64
#define ROWS (B_*N_)          // 16384
#define NBH  (B_*HEADS)       // 64

// ---------------- scratch (device globals: allocation-free) ----------------
__device__ float g_qkv[(size_t)ROWS * 3 * DIMM];        // qkv fp32
__device__ float g_qf [(size_t)B_*HEADS*N_*HD];
__device__ float g_kf [(size_t)B_*HEADS*N_*HD];
__device__ float g_vf [(size_t)B_*HEADS*N_*HD];
__device__ __nv_bfloat16 g_xh [(size_t)ROWS * DIMM];    // x split
__device__ __nv_bfloat16 g_xl [(size_t)ROWS * DIMM];
__device__ __nv_bfloat16 g_ah [(size_t)ROWS * DIMM];    // attn split (linattn out)
__device__ __nv_bfloat16 g_al [(size_t)ROWS * DIMM];
__device__ __nv_bfloat16 g_wqh[(size_t)3 * DIMM * DIMM]; // wqkv^T split [N][K]
__device__ __nv_bfloat16 g_wql[(size_t)3 * DIMM * DIMM];
__device__ __nv_bfloat16 g_woh[(size_t)DIMM * DIMM];     // wout^T split
__device__ __nv_bfloat16 g_wol[(size_t)DIMM * DIMM];

// ---------------- helpers ----------------------------------------------------
__device__ __forceinline__ uint32_t smem_u32(const void* p) {
    uint32_t a;
    asm("{ .reg .u64 t; cvta.to.shared.u64 t, %1; cvt.u32.u64 %0, t; }"
        : "=r"(a) : "l"(p));
    return a;
}
__device__ __forceinline__ void cp16(uint32_t s, const void* g) {
    asm volatile("cp.async.cg.shared.global [%0], [%1], 16;" :: "r"(s), "l"(g));
}
#define CP_COMMIT() asm volatile("cp.async.commit_group;" ::: "memory")
#define CP_WAIT(n)  asm volatile("cp.async.wait_group %0;" :: "n"(n) : "memory")
#define LDSM4(r0, r1, r2, r3, addr) asm volatile( \
    "ldmatrix.sync.aligned.m8n8.x4.shared.b16 {%0,%1,%2,%3}, [%4];" \
    : "=r"(r0), "=r"(r1), "=r"(r2), "=r"(r3) : "r"(addr))
__device__ __forceinline__ void mma16816(float* c, const uint32_t* a,
                                         const uint32_t* b) {
    asm volatile(
        "mma.sync.aligned.m16n8k16.row.col.f32.bf16.bf16.f32 "
        "{%0,%1,%2,%3}, {%4,%5,%6,%7}, {%8,%9}, {%0,%1,%2,%3};"
        : "+f"(c[0]), "+f"(c[1]), "+f"(c[2]), "+f"(c[3])
        : "r"(a[0]), "r"(a[1]), "r"(a[2]), "r"(a[3]), "r"(b[0]), "r"(b[1]));
}
__device__ __forceinline__ uint32_t swz(int r, int ck) {
    return (uint32_t)(((r >> 1) << 7) |
                      ((((((r & 1) << 2) | ck)) ^ ((r >> 1) & 7)) << 4));
}

// ---------------- split fp32 -> bf16 hi/lo ----------------------------------
__global__ void split_bf16(const float* __restrict__ in,
                           __nv_bfloat16* __restrict__ hi,
                           __nv_bfloat16* __restrict__ lo, int n4) {
    int i = blockIdx.x * blockDim.x + threadIdx.x;
    if (i >= n4) return;
    float4 v = ((const float4*)in)[i];
    __nv_bfloat16 h0 = __float2bfloat16(v.x), h1 = __float2bfloat16(v.y);
    __nv_bfloat16 h2 = __float2bfloat16(v.z), h3 = __float2bfloat16(v.w);
    __nv_bfloat16 l0 = __float2bfloat16(v.x - __bfloat162float(h0));
    __nv_bfloat16 l1 = __float2bfloat16(v.y - __bfloat162float(h1));
    __nv_bfloat16 l2 = __float2bfloat16(v.z - __bfloat162float(h2));
    __nv_bfloat16 l3 = __float2bfloat16(v.w - __bfloat162float(h3));
    ((ushort4*)hi)[i] = make_ushort4(__bfloat16_as_ushort(h0), __bfloat16_as_ushort(h1),
                                     __bfloat16_as_ushort(h2), __bfloat16_as_ushort(h3));
    ((ushort4*)lo)[i] = make_ushort4(__bfloat16_as_ushort(l0), __bfloat16_as_ushort(l1),
                                     __bfloat16_as_ushort(l2), __bfloat16_as_ushort(l3));
}

// ---------------- transpose + split: w[K][N] -> wt_hi/lo [N][K] --------------
__global__ void transpose_split(const float* __restrict__ w,
                                __nv_bfloat16* __restrict__ th,
                                __nv_bfloat16* __restrict__ tl, int K, int N) {
    __shared__ float t[32][33];
    int tx = threadIdx.x, ty = threadIdx.y;
    int x = blockIdx.x * 32 + tx;
#pragma unroll
    for (int j = 0; j < 32; j += 8) {
        int y = blockIdx.y * 32 + ty + j;
        t[ty + j][tx] = w[(size_t)y * N + x];
    }
    __syncthreads();
#pragma unroll
    for (int j = 0; j < 32; j += 8) {
        int n = blockIdx.x * 32 + ty + j;
        int k = blockIdx.y * 32 + tx;
        float v = t[tx][ty + j];
        __nv_bfloat16 h = __float2bfloat16(v);
        th[(size_t)n * K + k] = h;
        tl[(size_t)n * K + k] = __float2bfloat16(v - __bfloat162float(h));
    }
}

// ---------------- split-bf16 tensor-core GEMM (mma.sync) ---------------------
#define STAGE    32768
#define OFFS_AH  0
#define OFFS_AL  8192
#define OFFS_BH  16384
#define OFFS_BL  24576
#define GEMM_SMEM (2 * STAGE)

__global__ void __launch_bounds__(256, 2) mma_gemm(
    const __nv_bfloat16* __restrict__ Ah, const __nv_bfloat16* __restrict__ Al,
    const __nv_bfloat16* __restrict__ Bh, const __nv_bfloat16* __restrict__ Bl,
    float* __restrict__ C, int M, int N, int K) {
    extern __shared__ char sm[];
    const uint32_t sb = smem_u32(sm);
    const int tid = threadIdx.x;
    const int lane = tid & 31, wid = tid >> 5;
    const int warp_m = wid & 1, warp_n = wid >> 1;
    const int m0 = blockIdx.y * 128, n0 = blockIdx.x * 128;

    const int i0 = tid, i1 = tid + 256;
    const int lr0 = i0 >> 2, lc0 = i0 & 3;
    const int lr1 = i1 >> 2, lc1 = i1 & 3;
    const uint32_t so0 = swz(lr0, lc0), so1 = swz(lr1, lc1);

    uint32_t baseA[4], baseB[2];
#pragma unroll
    for (int mf = 0; mf < 4; mf++)
        baseA[mf] = swz(warp_m * 64 + mf * 16 + (lane & 15), lane >> 4);
#pragma unroll
    for (int p = 0; p < 2; p++)
        baseB[p] = swz(warp_n * 32 + p * 16 + ((lane >> 4) << 3) + (lane & 7),
                       (lane >> 3) & 1);

    float acc[4][4][4];
#pragma unroll
    for (int a = 0; a < 4; a++)
#pragma unroll
        for (int b = 0; b < 4; b++)
#pragma unroll
            for (int c = 0; c < 4; c++) acc[a][b][c] = 0.f;

    const int nIter = K >> 5;
    {
        uint32_t bs = sb;
        size_t a0 = (size_t)(m0 + lr0) * K + lc0 * 8;
        size_t a1 = (size_t)(m0 + lr1) * K + lc1 * 8;
        size_t b0 = (size_t)(n0 + lr0) * K + lc0 * 8;
        size_t b1 = (size_t)(n0 + lr1) * K + lc1 * 8;
        cp16(bs + OFFS_AH + so0, Ah + a0); cp16(bs + OFFS_AH + so1, Ah + a1);
        cp16(bs + OFFS_AL + so0, Al + a0); cp16(bs + OFFS_AL + so1, Al + a1);
        cp16(bs + OFFS_BH + so0, Bh + b0); cp16(bs + OFFS_BH + so1, Bh + b1);
        cp16(bs + OFFS_BL + so0, Bl + b0); cp16(bs + OFFS_BL + so1, Bl + b1);
        CP_COMMIT();
    }

    for (int it = 0; it < nIter; it++) {
        if (it + 1 < nIter) {
            int kk = (it + 1) << 5;
            uint32_t bs = sb + ((it + 1) & 1) * STAGE;
            size_t a0 = (size_t)(m0 + lr0) * K + kk + lc0 * 8;
            size_t a1 = (size_t)(m0 + lr1) * K + kk + lc1 * 8;
            size_t b0 = (size_t)(n0 + lr0) * K + kk + lc0 * 8;
            size_t b1 = (size_t)(n0 + lr1) * K + kk + lc1 * 8;
            cp16(bs + OFFS_AH + so0, Ah + a0); cp16(bs + OFFS_AH + so1, Ah + a1);
            cp16(bs + OFFS_AL + so0, Al + a0); cp16(bs + OFFS_AL + so1, Al + a1);
            cp16(bs + OFFS_BH + so0, Bh + b0); cp16(bs + OFFS_BH + so1, Bh + b1);
            cp16(bs + OFFS_BL + so0, Bl + b0); cp16(bs + OFFS_BL + so1, Bl + b1);
            CP_COMMIT();
            CP_WAIT(1);
        } else {
            CP_WAIT(0);
        }
        __syncthreads();

        const uint32_t ss = sb + (it & 1) * STAGE;
#pragma unroll
        for (int ks = 0; ks < 2; ks++) {
            const uint32_t kx = ks * 32;
            uint32_t bh[4][2], bl[4][2];
#pragma unroll
            for (int p = 0; p < 2; p++) {
                uint32_t r0, r1, r2, r3;
                LDSM4(r0, r1, r2, r3, ss + OFFS_BH + (baseB[p] ^ kx));
                bh[2 * p][0] = r0; bh[2 * p][1] = r1;
                bh[2 * p + 1][0] = r2; bh[2 * p + 1][1] = r3;
                LDSM4(r0, r1, r2, r3, ss + OFFS_BL + (baseB[p] ^ kx));
                bl[2 * p][0] = r0; bl[2 * p][1] = r1;
                bl[2 * p + 1][0] = r2; bl[2 * p + 1][1] = r3;
            }
#pragma unroll
            for (int mf = 0; mf < 4; mf++) {
                uint32_t ah[4], al[4];
                LDSM4(ah[0], ah[1], ah[2], ah[3], ss + OFFS_AH + (baseA[mf] ^ kx));
                LDSM4(al[0], al[1], al[2], al[3], ss + OFFS_AL + (baseA[mf] ^ kx));
#pragma unroll
                for (int nf = 0; nf < 4; nf++) {
                    mma16816(acc[mf][nf], ah, bh[nf]);
                    mma16816(acc[mf][nf], ah, bl[nf]);
                    mma16816(acc[mf][nf], al, bh[nf]);
                }
            }
        }
        __syncthreads();
    }

#pragma unroll
    for (int mf = 0; mf < 4; mf++) {
#pragma unroll
        for (int nf = 0; nf < 4; nf++) {
            int row = m0 + warp_m * 64 + mf * 16 + (lane >> 2);
            int col = n0 + warp_n * 32 + nf * 8 + 2 * (lane & 3);
            *(float2*)(C + (size_t)row * N + col) =
                make_float2(acc[mf][nf][0], acc[mf][nf][1]);
            *(float2*)(C + (size_t)(row + 8) * N + col) =
                make_float2(acc[mf][nf][2], acc[mf][nf][3]);
        }
    }
}

// ---------------- RoPE + ELU feature map + transpose to (B,H,N,D) ----------
__global__ void rope_elu(const float* __restrict__ qkv,
                         float* __restrict__ qf, float* __restrict__ kf,
                         float* __restrict__ vf) {
    int idx = blockIdx.x * blockDim.x + threadIdx.x;
    const int total = B_ * N_ * HEADS * 32;
    if (idx >= total) return;
    const int d2 = idx & 31;
    const int h  = (idx >> 5) & 15;
    const int n  = (idx >> 9) & 4095;
    const int b  = idx >> 21;

    size_t base = (size_t)(b * N_ + n) * (3 * DIMM);
    int c1 = h * 64 + d2;
    float q1 = qkv[base + c1],            q2 = qkv[base + c1 + 32];
    float k1 = qkv[base + 1024 + c1],     k2 = qkv[base + 1024 + c1 + 32];
    float v1 = qkv[base + 2048 + c1],     v2 = qkv[base + 2048 + c1 + 32];

    float inv = powf(10000.f, -(float)d2 * (1.f / 32.f));
    float ang = (float)n * inv;
    float cs = cosf(ang), sn = sinf(ang);
    float qr1 = q1 * cs - q2 * sn, qr2 = q1 * sn + q2 * cs;
    float kr1 = k1 * cs - k2 * sn, kr2 = k1 * sn + k2 * cs;

    const float SC = 0.35355339059327373f;
    float y;
    y = qr1 * SC; float fq1 = (y > 0.f) ? y + 1.f : expf(y);
    y = qr2 * SC; float fq2 = (y > 0.f) ? y + 1.f : expf(y);
    y = kr1 * SC; float fk1 = (y > 0.f) ? y + 1.f : expf(y);
    y = kr2 * SC; float fk2 = (y > 0.f) ? y + 1.f : expf(y);

    size_t ob = ((size_t)(b * HEADS + h) * N_ + n) * HD;
    qf[ob + d2] = fq1;  qf[ob + d2 + 32] = fq2;
    kf[ob + d2] = fk1;  kf[ob + d2 + 32] = fk2;
    vf[ob + d2] = v1;   vf[ob + d2 + 32] = v2;
}

// ---------------- chunked causal linear attention, m-split x2 ----------------
// grid = NBH*2. Block (bh, mh) owns V columns [mh*32, mh*32+32).
// S^T and denom duplicated across the two blocks of a bh (cheap vs 2x SMs).
// Epilogue emits bf16 hi/lo split of attn directly.
#define ATTN_SMEM ((4 * 4096 + 2 * 2048 + 128) * 4)   // 82432 B
__global__ void __launch_bounds__(256) linattn(const float* __restrict__ qf,
                                               const float* __restrict__ kf,
                                               const float* __restrict__ vf,
                                               __nv_bfloat16* __restrict__ ah,
                                               __nv_bfloat16* __restrict__ al) {
    extern __shared__ float smf[];
    float* QsT = smf;              // [d][i]   4096
    float* Ks  = QsT + 4096;       // [i][d]   4096
    float* KsT = Ks + 4096;        // [d][j]   4096
    float* STs = KsT + 4096;       // [j][i]   4096
    float* Vs  = STs + 4096;       // [j][m32] 2048
    float* KV  = Vs + 2048;        // [d][m32] 2048
    float* kss = KV + 2048;        // [64]
    float* den = kss + 64;         // [64]

    const int tid = threadIdx.x;
    const int bh = blockIdx.x >> 1;
    const int mh = blockIdx.x & 1;
    const int b = bh >> 4, h = bh & 15;
    const float* qb = qf + (size_t)bh * N_ * HD;
    const float* kb = kf + (size_t)bh * N_ * HD;
    const float* vb = vf + (size_t)bh * N_ * HD;

    for (int i = tid; i < 2048; i += 256) KV[i] = 0.f;
    if (tid < 64) kss[tid] = 0.f;
    __syncthreads();

    const int li = tid >> 2, lq = (tid & 3) * 16;    // Q/K load mapping
    const int lv = (tid & 3) * 8;                    // V load mapping (32 cols)
    const int g1 = tid >> 4, g2 = tid & 15;          // S^T 16x16 of 4x4
    const int oi = (tid >> 3) * 2, om = (tid & 7) * 4;  // out: 2i x 4m
    const int ud = (tid >> 3) * 2, um = (tid & 7) * 4;  // update: 2d x 4m

    for (int c = 0; c < 64; c++) {
        const int n0 = c * 64;
        // ---- load chunk ----
        {
            const float* qrow = qb + (size_t)(n0 + li) * HD + lq;
            const float* krow = kb + (size_t)(n0 + li) * HD + lq;
#pragma unroll
            for (int t = 0; t < 4; t++) {
                int d0 = lq + t * 4;
                float4 qv = *(const float4*)(qrow + t * 4);
                QsT[(d0 + 0) * 64 + li] = qv.x;
                QsT[(d0 + 1) * 64 + li] = qv.y;
                QsT[(d0 + 2) * 64 + li] = qv.z;
                QsT[(d0 + 3) * 64 + li] = qv.w;
                float4 kv4 = *(const float4*)(krow + t * 4);
                *(float4*)&Ks[li * 64 + d0] = kv4;
                KsT[(d0 + 0) * 64 + li] = kv4.x;
                KsT[(d0 + 1) * 64 + li] = kv4.y;
                KsT[(d0 + 2) * 64 + li] = kv4.z;
                KsT[(d0 + 3) * 64 + li] = kv4.w;
            }
            const float* vrow = vb + (size_t)(n0 + li) * HD + mh * 32 + lv;
#pragma unroll
            for (int t = 0; t < 2; t++)
                *(float4*)&Vs[li * 32 + lv + t * 4] = *(const float4*)(vrow + t * 4);
        }
        __syncthreads();
        // ---- S^T[j][i] = sum_d Q[i][d] K[j][d], causal mask j<=i ----
        {
            float accS[16];
#pragma unroll
            for (int z = 0; z < 16; z++) accS[z] = 0.f;
            for (int d = 0; d < 64; d++) {
                float4 qv = *(float4*)&QsT[d * 64 + g2 * 4];
                float4 kk = *(float4*)&KsT[d * 64 + g1 * 4];
                float qa[4] = {qv.x, qv.y, qv.z, qv.w};
                float ka[4] = {kk.x, kk.y, kk.z, kk.w};
#pragma unroll
                for (int jj = 0; jj < 4; jj++)
#pragma unroll
                    for (int ii = 0; ii < 4; ii++)
                        accS[jj * 4 + ii] += ka[jj] * qa[ii];
            }
#pragma unroll
            for (int jj = 0; jj < 4; jj++)
#pragma unroll
                for (int ii = 0; ii < 4; ii++) {
                    int j = g1 * 4 + jj, i = g2 * 4 + ii;
                    STs[j * 64 + i] = (j <= i) ? accS[jj * 4 + ii] : 0.f;
                }
        }
        __syncthreads();
        // ---- denom[i] = max(q_i . ks_prev + rowsum_{j<=i} S, 1e-6) ----
        if (tid < 64) {
            int i = tid;
            float s = 0.f;
            for (int d = 0; d < 64; d++) s += QsT[d * 64 + i] * kss[d];
            for (int j = 0; j <= i; j++) s += STs[j * 64 + i];
            den[i] = fmaxf(s, 1e-6f);
        }
        __syncthreads();
        // ---- out[i][m] = (Q.KV_prev + S.V)/den; fused bf16 hi/lo store ----
        {
            float acc[2][4];
#pragma unroll
            for (int z = 0; z < 4; z++) { acc[0][z] = 0.f; acc[1][z] = 0.f; }
            for (int d = 0; d < 64; d++) {
                float2 q2 = *(float2*)&QsT[d * 64 + oi];
                float4 kv4 = *(float4*)&KV[d * 32 + om];
                acc[0][0] += q2.x * kv4.x; acc[0][1] += q2.x * kv4.y;
                acc[0][2] += q2.x * kv4.z; acc[0][3] += q2.x * kv4.w;
                acc[1][0] += q2.y * kv4.x; acc[1][1] += q2.y * kv4.y;
                acc[1][2] += q2.y * kv4.z; acc[1][3] += q2.y * kv4.w;
            }
            for (int j = 0; j < 64; j++) {
                float2 s2 = *(float2*)&STs[j * 64 + oi];
                float4 v4 = *(float4*)&Vs[j * 32 + om];
                acc[0][0] += s2.x * v4.x; acc[0][1] += s2.x * v4.y;
                acc[0][2] += s2.x * v4.z; acc[0][3] += s2.x * v4.w;
                acc[1][0] += s2.y * v4.x; acc[1][1] += s2.y * v4.y;
                acc[1][2] += s2.y * v4.z; acc[1][3] += s2.y * v4.w;
            }
#pragma unroll
            for (int ii = 0; ii < 2; ii++) {
                int i = oi + ii;
                float inv = 1.f / den[i];
                float v0 = acc[ii][0] * inv, v1 = acc[ii][1] * inv;
                float v2 = acc[ii][2] * inv, v3 = acc[ii][3] * inv;
                __nv_bfloat16 h0 = __float2bfloat16(v0), h1 = __float2bfloat16(v1);
                __nv_bfloat16 h2 = __float2bfloat16(v2), h3 = __float2bfloat16(v3);
                size_t ro = (size_t)(b * N_ + n0 + i) * DIMM + h * HD + mh * 32 + om;
                *(ushort4*)(ah + ro) =
                    make_ushort4(__bfloat16_as_ushort(h0), __bfloat16_as_ushort(h1),
                                 __bfloat16_as_ushort(h2), __bfloat16_as_ushort(h3));
                *(ushort4*)(al + ro) = make_ushort4(
                    __bfloat16_as_ushort(__float2bfloat16(v0 - __bfloat162float(h0))),
                    __bfloat16_as_ushort(__float2bfloat16(v1 - __bfloat162float(h1))),
                    __bfloat16_as_ushort(__float2bfloat16(v2 - __bfloat162float(h2))),
                    __bfloat16_as_ushort(__float2bfloat16(v3 - __bfloat162float(h3))));
            }
        }
        __syncthreads();
        // ---- state update: KV += K^T V ; ks += colsum(K) ----
        {
            float acc[2][4];
#pragma unroll
            for (int dd = 0; dd < 2; dd++) {
                float4 t = *(float4*)&KV[(ud + dd) * 32 + um];
                acc[dd][0] = t.x; acc[dd][1] = t.y; acc[dd][2] = t.z; acc[dd][3] = t.w;
            }
            for (int i = 0; i < 64; i++) {
                float2 k2 = *(float2*)&Ks[i * 64 + ud];
                float4 v4 = *(float4*)&Vs[i * 32 + um];
                acc[0][0] += k2.x * v4.x; acc[0][1] += k2.x * v4.y;
                acc[0][2] += k2.x * v4.z; acc[0][3] += k2.x * v4.w;
                acc[1][0] += k2.y * v4.x; acc[1][1] += k2.y * v4.y;
                acc[1][2] += k2.y * v4.z; acc[1][3] += k2.y * v4.w;
            }
#pragma unroll
            for (int dd = 0; dd < 2; dd++)
                *(float4*)&KV[(ud + dd) * 32 + um] =
                    make_float4(acc[dd][0], acc[dd][1], acc[dd][2], acc[dd][3]);
            if (tid < 64) {
                int d = tid;
                float s = kss[d];
                for (int i = 0; i < 64; i++) s += Ks[i * 64 + d];
                kss[d] = s;
            }
        }
        __syncthreads();
    }
}

// ---------------- launch -----------------------------------------------------
extern "C" void kernel_launch(void* const* d_in, const int* in_sizes, int n_in,
                              void* d_out, int out_size) {
    const float* x    = (const float*)d_in[0];
    const float* wqkv = (const float*)d_in[1];
    const float* wout = (const float*)d_in[2];
    float* out = (float*)d_out;

    float *qkv, *qf, *kf, *vf;
    __nv_bfloat16 *xh, *xl, *ah, *al, *wqh, *wql, *woh, *wol;
    cudaGetSymbolAddress((void**)&qkv, g_qkv);
    cudaGetSymbolAddress((void**)&qf,  g_qf);
    cudaGetSymbolAddress((void**)&kf,  g_kf);
    cudaGetSymbolAddress((void**)&vf,  g_vf);
    cudaGetSymbolAddress((void**)&xh,  g_xh);
    cudaGetSymbolAddress((void**)&xl,  g_xl);
    cudaGetSymbolAddress((void**)&ah,  g_ah);
    cudaGetSymbolAddress((void**)&al,  g_al);
    cudaGetSymbolAddress((void**)&wqh, g_wqh);
    cudaGetSymbolAddress((void**)&wql, g_wql);
    cudaGetSymbolAddress((void**)&woh, g_woh);
    cudaGetSymbolAddress((void**)&wol, g_wol);

    cudaFuncSetAttribute(mma_gemm, cudaFuncAttributeMaxDynamicSharedMemorySize,
                         GEMM_SMEM);
    cudaFuncSetAttribute(linattn, cudaFuncAttributeMaxDynamicSharedMemorySize,
                         ATTN_SMEM);

    // split x; transpose+split weights
    {
        int n4 = ROWS * DIMM / 4;
        split_bf16<<<(n4 + 255) / 256, 256>>>(x, xh, xl, n4);
        transpose_split<<<dim3(3 * DIMM / 32, DIMM / 32), dim3(32, 8)>>>(
            wqkv, wqh, wql, DIMM, 3 * DIMM);
        transpose_split<<<dim3(DIMM / 32, DIMM / 32), dim3(32, 8)>>>(
            wout, woh, wol, DIMM, DIMM);
    }
    // 1) qkv = x @ w_qkv   (tensor cores)
    mma_gemm<<<dim3(3 * DIMM / 128, ROWS / 128), 256, GEMM_SMEM>>>(
        xh, xl, wqh, wql, qkv, ROWS, 3 * DIMM, DIMM);
    // 2) RoPE + ELU + transpose
    {
        int total = B_ * N_ * HEADS * 32;
        rope_elu<<<(total + 255) / 256, 256>>>(qkv, qf, kf, vf);
    }
    // 3) chunked linear attention, m-split x2 (emits bf16 hi/lo directly)
    linattn<<<NBH * 2, 256, ATTN_SMEM>>>(qf, kf, vf, ah, al);
    // 4) out = attn @ w_out (tensor cores)
    mma_gemm<<<dim3(DIMM / 128, ROWS / 128), 256, GEMM_SMEM>>>(
        ah, al, woh, wol, out, ROWS, DIMM, DIMM);
}

// round 11
// speedup vs baseline: 1.3379x; 1.1122x over previous
#include <cuda_runtime.h>
#include <cuda_bf16.h>
#include <math.h>
#include <stdint.h>

#define B_   4
#define N_   4096
#define DIMM 1024
#define HEADS 16
#define HD   64
#define ROWS (B_*N_)          // 16384
#define NBH  (B_*HEADS)       // 64

// ---------------- scratch (device globals: allocation-free) ----------------
__device__ float g_qkv[(size_t)ROWS * 3 * DIMM];        // qkv fp32
__device__ __nv_bfloat16 g_Qh[(size_t)NBH * N_ * HD];   // featurized q/k/v bf16 splits
__device__ __nv_bfloat16 g_Ql[(size_t)NBH * N_ * HD];
__device__ __nv_bfloat16 g_Kh[(size_t)NBH * N_ * HD];
__device__ __nv_bfloat16 g_Kl[(size_t)NBH * N_ * HD];
__device__ __nv_bfloat16 g_Vh[(size_t)NBH * N_ * HD];
__device__ __nv_bfloat16 g_Vl[(size_t)NBH * N_ * HD];
__device__ __nv_bfloat16 g_xh [(size_t)ROWS * DIMM];    // x split
__device__ __nv_bfloat16 g_xl [(size_t)ROWS * DIMM];
__device__ __nv_bfloat16 g_ah [(size_t)ROWS * DIMM];    // attn split (linattn out)
__device__ __nv_bfloat16 g_al [(size_t)ROWS * DIMM];
__device__ __nv_bfloat16 g_wqh[(size_t)3 * DIMM * DIMM]; // wqkv^T split [N][K]
__device__ __nv_bfloat16 g_wql[(size_t)3 * DIMM * DIMM];
__device__ __nv_bfloat16 g_woh[(size_t)DIMM * DIMM];     // wout^T split
__device__ __nv_bfloat16 g_wol[(size_t)DIMM * DIMM];

// ---------------- helpers ----------------------------------------------------
__device__ __forceinline__ uint32_t smem_u32(const void* p) {
    uint32_t a;
    asm("{ .reg .u64 t; cvta.to.shared.u64 t, %1; cvt.u32.u64 %0, t; }"
        : "=r"(a) : "l"(p));
    return a;
}
__device__ __forceinline__ void cp16(uint32_t s, const void* g) {
    asm volatile("cp.async.cg.shared.global [%0], [%1], 16;" :: "r"(s), "l"(g));
}
#define CP_COMMIT() asm volatile("cp.async.commit_group;" ::: "memory")
#define CP_WAIT(n)  asm volatile("cp.async.wait_group %0;" :: "n"(n) : "memory")
#define LDSM4(r0, r1, r2, r3, addr) asm volatile( \
    "ldmatrix.sync.aligned.m8n8.x4.shared.b16 {%0,%1,%2,%3}, [%4];" \
    : "=r"(r0), "=r"(r1), "=r"(r2), "=r"(r3) : "r"(addr))
__device__ __forceinline__ void mma16816(float* c, const uint32_t* a,
                                         const uint32_t* b) {
    asm volatile(
        "mma.sync.aligned.m16n8k16.row.col.f32.bf16.bf16.f32 "
        "{%0,%1,%2,%3}, {%4,%5,%6,%7}, {%8,%9}, {%0,%1,%2,%3};"
        : "+f"(c[0]), "+f"(c[1]), "+f"(c[2]), "+f"(c[3])
        : "r"(a[0]), "r"(a[1]), "r"(a[2]), "r"(a[3]), "r"(b[0]), "r"(b[1]));
}
// 64x32(bf16)=64B-row swizzle (GEMM tiles)
__device__ __forceinline__ uint32_t swz(int r, int ck) {
    return (uint32_t)(((r >> 1) << 7) |
                      ((((((r & 1) << 2) | ck)) ^ ((r >> 1) & 7)) << 4));
}
// 64x64(bf16)=128B-row swizzle (attention tiles); ck in 0..7
#define SWZ64(r, ck) ((uint32_t)((r) * 128 + ((((ck) ^ ((r) & 7))) << 4)))

__device__ __forceinline__ float bfu(unsigned short u) {
    return __bfloat162float(__ushort_as_bfloat16(u));
}
__device__ __forceinline__ void split2u(float v, unsigned short& hh,
                                        unsigned short& ll) {
    __nv_bfloat16 b = __float2bfloat16(v);
    hh = __bfloat16_as_ushort(b);
    ll = __bfloat16_as_ushort(__float2bfloat16(v - __bfloat162float(b)));
}

// ---------------- split fp32 -> bf16 hi/lo ----------------------------------
__global__ void split_bf16(const float* __restrict__ in,
                           __nv_bfloat16* __restrict__ hi,
                           __nv_bfloat16* __restrict__ lo, int n4) {
    int i = blockIdx.x * blockDim.x + threadIdx.x;
    if (i >= n4) return;
    float4 v = ((const float4*)in)[i];
    unsigned short h0, l0, h1, l1, h2, l2, h3, l3;
    split2u(v.x, h0, l0); split2u(v.y, h1, l1);
    split2u(v.z, h2, l2); split2u(v.w, h3, l3);
    ((ushort4*)hi)[i] = make_ushort4(h0, h1, h2, h3);
    ((ushort4*)lo)[i] = make_ushort4(l0, l1, l2, l3);
}

// ---------------- transpose + split: w[K][N] -> wt_hi/lo [N][K] --------------
__global__ void transpose_split(const float* __restrict__ w,
                                __nv_bfloat16* __restrict__ th,
                                __nv_bfloat16* __restrict__ tl, int K, int N) {
    __shared__ float t[32][33];
    int tx = threadIdx.x, ty = threadIdx.y;
    int x = blockIdx.x * 32 + tx;
#pragma unroll
    for (int j = 0; j < 32; j += 8) {
        int y = blockIdx.y * 32 + ty + j;
        t[ty + j][tx] = w[(size_t)y * N + x];
    }
    __syncthreads();
#pragma unroll
    for (int j = 0; j < 32; j += 8) {
        int n = blockIdx.x * 32 + ty + j;
        int k = blockIdx.y * 32 + tx;
        float v = t[tx][ty + j];
        __nv_bfloat16 h = __float2bfloat16(v);
        th[(size_t)n * K + k] = h;
        tl[(size_t)n * K + k] = __float2bfloat16(v - __bfloat162float(h));
    }
}

// ---------------- split-bf16 tensor-core GEMM (mma.sync) ---------------------
#define STAGE    32768
#define OFFS_AH  0
#define OFFS_AL  8192
#define OFFS_BH  16384
#define OFFS_BL  24576
#define GEMM_SMEM (2 * STAGE)

__global__ void __launch_bounds__(256, 2) mma_gemm(
    const __nv_bfloat16* __restrict__ Ah, const __nv_bfloat16* __restrict__ Al,
    const __nv_bfloat16* __restrict__ Bh, const __nv_bfloat16* __restrict__ Bl,
    float* __restrict__ C, int M, int N, int K) {
    extern __shared__ char sm[];
    const uint32_t sb = smem_u32(sm);
    const int tid = threadIdx.x;
    const int lane = tid & 31, wid = tid >> 5;
    const int warp_m = wid & 1, warp_n = wid >> 1;
    const int m0 = blockIdx.y * 128, n0 = blockIdx.x * 128;

    const int i0 = tid, i1 = tid + 256;
    const int lr0 = i0 >> 2, lc0 = i0 & 3;
    const int lr1 = i1 >> 2, lc1 = i1 & 3;
    const uint32_t so0 = swz(lr0, lc0), so1 = swz(lr1, lc1);

    uint32_t baseA[4], baseB[2];
#pragma unroll
    for (int mf = 0; mf < 4; mf++)
        baseA[mf] = swz(warp_m * 64 + mf * 16 + (lane & 15), lane >> 4);
#pragma unroll
    for (int p = 0; p < 2; p++)
        baseB[p] = swz(warp_n * 32 + p * 16 + ((lane >> 4) << 3) + (lane & 7),
                       (lane >> 3) & 1);

    float acc[4][4][4];
#pragma unroll
    for (int a = 0; a < 4; a++)
#pragma unroll
        for (int b = 0; b < 4; b++)
#pragma unroll
            for (int c = 0; c < 4; c++) acc[a][b][c] = 0.f;

    const int nIter = K >> 5;
    {
        uint32_t bs = sb;
        size_t a0 = (size_t)(m0 + lr0) * K + lc0 * 8;
        size_t a1 = (size_t)(m0 + lr1) * K + lc1 * 8;
        size_t b0 = (size_t)(n0 + lr0) * K + lc0 * 8;
        size_t b1 = (size_t)(n0 + lr1) * K + lc1 * 8;
        cp16(bs + OFFS_AH + so0, Ah + a0); cp16(bs + OFFS_AH + so1, Ah + a1);
        cp16(bs + OFFS_AL + so0, Al + a0); cp16(bs + OFFS_AL + so1, Al + a1);
        cp16(bs + OFFS_BH + so0, Bh + b0); cp16(bs + OFFS_BH + so1, Bh + b1);
        cp16(bs + OFFS_BL + so0, Bl + b0); cp16(bs + OFFS_BL + so1, Bl + b1);
        CP_COMMIT();
    }

    for (int it = 0; it < nIter; it++) {
        if (it + 1 < nIter) {
            int kk = (it + 1) << 5;
            uint32_t bs = sb + ((it + 1) & 1) * STAGE;
            size_t a0 = (size_t)(m0 + lr0) * K + kk + lc0 * 8;
            size_t a1 = (size_t)(m0 + lr1) * K + kk + lc1 * 8;
            size_t b0 = (size_t)(n0 + lr0) * K + kk + lc0 * 8;
            size_t b1 = (size_t)(n0 + lr1) * K + kk + lc1 * 8;
            cp16(bs + OFFS_AH + so0, Ah + a0); cp16(bs + OFFS_AH + so1, Ah + a1);
            cp16(bs + OFFS_AL + so0, Al + a0); cp16(bs + OFFS_AL + so1, Al + a1);
            cp16(bs + OFFS_BH + so0, Bh + b0); cp16(bs + OFFS_BH + so1, Bh + b1);
            cp16(bs + OFFS_BL + so0, Bl + b0); cp16(bs + OFFS_BL + so1, Bl + b1);
            CP_COMMIT();
            CP_WAIT(1);
        } else {
            CP_WAIT(0);
        }
        __syncthreads();

        const uint32_t ss = sb + (it & 1) * STAGE;
#pragma unroll
        for (int ks = 0; ks < 2; ks++) {
            const uint32_t kx = ks * 32;
            uint32_t bh[4][2], bl[4][2];
#pragma unroll
            for (int p = 0; p < 2; p++) {
                uint32_t r0, r1, r2, r3;
                LDSM4(r0, r1, r2, r3, ss + OFFS_BH + (baseB[p] ^ kx));
                bh[2 * p][0] = r0; bh[2 * p][1] = r1;
                bh[2 * p + 1][0] = r2; bh[2 * p + 1][1] = r3;
                LDSM4(r0, r1, r2, r3, ss + OFFS_BL + (baseB[p] ^ kx));
                bl[2 * p][0] = r0; bl[2 * p][1] = r1;
                bl[2 * p + 1][0] = r2; bl[2 * p + 1][1] = r3;
            }
#pragma unroll
            for (int mf = 0; mf < 4; mf++) {
                uint32_t ah[4], al[4];
                LDSM4(ah[0], ah[1], ah[2], ah[3], ss + OFFS_AH + (baseA[mf] ^ kx));
                LDSM4(al[0], al[1], al[2], al[3], ss + OFFS_AL + (baseA[mf] ^ kx));
#pragma unroll
                for (int nf = 0; nf < 4; nf++) {
                    mma16816(acc[mf][nf], ah, bh[nf]);
                    mma16816(acc[mf][nf], ah, bl[nf]);
                    mma16816(acc[mf][nf], al, bh[nf]);
                }
            }
        }
        __syncthreads();
    }

#pragma unroll
    for (int mf = 0; mf < 4; mf++) {
#pragma unroll
        for (int nf = 0; nf < 4; nf++) {
            int row = m0 + warp_m * 64 + mf * 16 + (lane >> 2);
            int col = n0 + warp_n * 32 + nf * 8 + 2 * (lane & 3);
            *(float2*)(C + (size_t)row * N + col) =
                make_float2(acc[mf][nf][0], acc[mf][nf][1]);
            *(float2*)(C + (size_t)(row + 8) * N + col) =
                make_float2(acc[mf][nf][2], acc[mf][nf][3]);
        }
    }
}

// ---------------- RoPE + ELU feature map -> bf16 hi/lo (B,H,N,D) ------------
__global__ void rope_elu(const float* __restrict__ qkv,
                         __nv_bfloat16* __restrict__ Qh, __nv_bfloat16* __restrict__ Ql,
                         __nv_bfloat16* __restrict__ Kh, __nv_bfloat16* __restrict__ Kl,
                         __nv_bfloat16* __restrict__ Vh, __nv_bfloat16* __restrict__ Vl) {
    int idx = blockIdx.x * blockDim.x + threadIdx.x;
    const int total = B_ * N_ * HEADS * 32;
    if (idx >= total) return;
    const int d2 = idx & 31;
    const int h  = (idx >> 5) & 15;
    const int n  = (idx >> 9) & 4095;
    const int b  = idx >> 21;

    size_t base = (size_t)(b * N_ + n) * (3 * DIMM);
    int c1 = h * 64 + d2;
    float q1 = qkv[base + c1],            q2 = qkv[base + c1 + 32];
    float k1 = qkv[base + 1024 + c1],     k2 = qkv[base + 1024 + c1 + 32];
    float v1 = qkv[base + 2048 + c1],     v2 = qkv[base + 2048 + c1 + 32];

    float inv = powf(10000.f, -(float)d2 * (1.f / 32.f));
    float ang = (float)n * inv;
    float cs = cosf(ang), sn = sinf(ang);
    float qr1 = q1 * cs - q2 * sn, qr2 = q1 * sn + q2 * cs;
    float kr1 = k1 * cs - k2 * sn, kr2 = k1 * sn + k2 * cs;

    const float SC = 0.35355339059327373f;
    float y;
    y = qr1 * SC; float fq1 = (y > 0.f) ? y + 1.f : expf(y);
    y = qr2 * SC; float fq2 = (y > 0.f) ? y + 1.f : expf(y);
    y = kr1 * SC; float fk1 = (y > 0.f) ? y + 1.f : expf(y);
    y = kr2 * SC; float fk2 = (y > 0.f) ? y + 1.f : expf(y);

    size_t ob = ((size_t)((b * HEADS + h)) * N_ + n) * HD;
    unsigned short hh, ll;
    split2u(fq1, hh, ll);
    ((unsigned short*)Qh)[ob + d2] = hh;      ((unsigned short*)Ql)[ob + d2] = ll;
    split2u(fq2, hh, ll);
    ((unsigned short*)Qh)[ob + d2 + 32] = hh; ((unsigned short*)Ql)[ob + d2 + 32] = ll;
    split2u(fk1, hh, ll);
    ((unsigned short*)Kh)[ob + d2] = hh;      ((unsigned short*)Kl)[ob + d2] = ll;
    split2u(fk2, hh, ll);
    ((unsigned short*)Kh)[ob + d2 + 32] = hh; ((unsigned short*)Kl)[ob + d2 + 32] = ll;
    split2u(v1, hh, ll);
    ((unsigned short*)Vh)[ob + d2] = hh;      ((unsigned short*)Vl)[ob + d2] = ll;
    split2u(v2, hh, ll);
    ((unsigned short*)Vh)[ob + d2 + 32] = hh; ((unsigned short*)Vl)[ob + d2 + 32] = ll;
}

// ---------------- mma-based chunked causal linear attention ------------------
// smem layout (bytes):
#define T_QH 0
#define T_QL 8192
#define T_KH 16384
#define T_KL 24576
#define T_VH 32768
#define T_VL 40960
#define BUFSZ 49152
#define O_KTH (2*BUFSZ)            // 98304
#define O_KTL (O_KTH + 8192)
#define O_VTH (O_KTL + 8192)
#define O_VTL (O_VTH + 8192)
#define O_SH  (O_VTL + 8192)       // 131072
#define O_SL  (O_SH + 8192)
#define O_KVH (O_SL + 8192)        // 147456
#define O_KVL (O_KVH + 8192)
#define O_KVF (O_KVL + 8192)       // 163840 (fp32 16K)
#define O_KS  (O_KVF + 16384)      // 180224
#define O_DEN (O_KS + 256)
#define O_DENP (O_DEN + 256)
#define LA_SMEM (O_DENP + 1024)    // 181760

// 3-term 64x64x64: acc[2][2][4] += (Ah+Al)(Bh+Bl)^T, tiles row-major k=64.
__device__ __forceinline__ void mm64(uint32_t aHt, uint32_t aLt,
                                     uint32_t bHt, uint32_t bLt,
                                     float (*acc)[2][4], int wm, int wn, int lane) {
    const uint32_t aOff0 = SWZ64(wm * 32 + (lane & 15), (lane >> 4));
    const uint32_t aOff1 = SWZ64(wm * 32 + 16 + (lane & 15), (lane >> 4));
    const uint32_t bOff  = SWZ64(wn * 16 + ((lane >> 4) << 3) + (lane & 7),
                                 (lane >> 3) & 1);
#pragma unroll
    for (int kx = 0; kx < 4; kx++) {
        const uint32_t x = kx << 5;
        uint32_t BH[2][2], BL[2][2], r0, r1, r2, r3;
        LDSM4(r0, r1, r2, r3, bHt + (bOff ^ x));
        BH[0][0] = r0; BH[0][1] = r1; BH[1][0] = r2; BH[1][1] = r3;
        LDSM4(r0, r1, r2, r3, bLt + (bOff ^ x));
        BL[0][0] = r0; BL[0][1] = r1; BL[1][0] = r2; BL[1][1] = r3;
#pragma unroll
        for (int mf = 0; mf < 2; mf++) {
            uint32_t ao = (mf ? aOff1 : aOff0) ^ x;
            uint32_t AH[4], AL[4];
            LDSM4(AH[0], AH[1], AH[2], AH[3], aHt + ao);
            LDSM4(AL[0], AL[1], AL[2], AL[3], aLt + ao);
#pragma unroll
            for (int nf = 0; nf < 2; nf++) {
                mma16816(acc[mf][nf], AH, BH[nf]);
                mma16816(acc[mf][nf], AH, BL[nf]);
                mma16816(acc[mf][nf], AL, BH[nf]);
            }
        }
    }
}

__device__ __forceinline__ void load_tile64(uint32_t dst,
                                            const __nv_bfloat16* g,
                                            size_t rowbase, int tid) {
#pragma unroll
    for (int uu = 0; uu < 2; uu++) {
        int u = tid + uu * 256;
        int r = u >> 3, ck = u & 7;
        cp16(dst + SWZ64(r, ck), g + rowbase + r * 64 + ck * 8);
    }
}

__global__ void __launch_bounds__(256) linattn_mma(
    const __nv_bfloat16* __restrict__ Qh, const __nv_bfloat16* __restrict__ Ql,
    const __nv_bfloat16* __restrict__ Kh, const __nv_bfloat16* __restrict__ Kl,
    const __nv_bfloat16* __restrict__ Vh, const __nv_bfloat16* __restrict__ Vl,
    __nv_bfloat16* __restrict__ ah, __nv_bfloat16* __restrict__ al) {
    extern __shared__ __align__(128) char smx[];
    const uint32_t sb = smem_u32(smx);
    const int tid = threadIdx.x;
    const int lane = tid & 31, wid = tid >> 5;
    const int wm = wid & 1, wn = wid >> 1;
    const int bh = blockIdx.x;
    const int bIdx = bh >> 4, hIdx = bh & 15;
    const size_t gb = (size_t)bh * N_ * HD;

    float* ksp  = (float*)(smx + O_KS);
    float* denp = (float*)(smx + O_DENP);
    float* denv = (float*)(smx + O_DEN);

    // init state
    for (int i = tid; i < 4096; i += 256) {
        *(float*)(smx + O_KVF + i * 4) = 0.f;
        *(unsigned short*)(smx + O_KVH + i * 2) = 0;
        *(unsigned short*)(smx + O_KVL + i * 2) = 0;
    }
    if (tid < 64) ksp[tid] = 0.f;

    // prefetch chunk 0
    load_tile64(sb + T_QH, Qh, gb, tid);
    load_tile64(sb + T_QL, Ql, gb, tid);
    load_tile64(sb + T_KH, Kh, gb, tid);
    load_tile64(sb + T_KL, Kl, gb, tid);
    load_tile64(sb + T_VH, Vh, gb, tid);
    load_tile64(sb + T_VL, Vl, gb, tid);
    CP_COMMIT();
    __syncthreads();

    for (int ch = 0; ch < 64; ch++) {
        const int n0 = ch * 64;
        const uint32_t bo = (ch & 1) * BUFSZ;
        CP_WAIT(0);
        __syncthreads();

        // build K^T, V^T in smem
        for (int idx = tid; idx < 4096; idx += 256) {
            int i = idx >> 6, d = idx & 63;
            uint32_t ro = SWZ64(i, d >> 3) + (d & 7) * 2;
            uint32_t wo = SWZ64(d, i >> 3) + (i & 7) * 2;
            *(unsigned short*)(smx + O_KTH + wo) = *(unsigned short*)(smx + bo + T_KH + ro);
            *(unsigned short*)(smx + O_KTL + wo) = *(unsigned short*)(smx + bo + T_KL + ro);
            *(unsigned short*)(smx + O_VTH + wo) = *(unsigned short*)(smx + bo + T_VH + ro);
            *(unsigned short*)(smx + O_VTL + wo) = *(unsigned short*)(smx + bo + T_VL + ro);
        }
        // prefetch next chunk
        if (ch + 1 < 64) {
            const uint32_t bo2 = ((ch + 1) & 1) * BUFSZ;
            size_t rb = gb + (size_t)(n0 + 64) * HD;
            load_tile64(sb + bo2 + T_QH, Qh, rb, tid);
            load_tile64(sb + bo2 + T_QL, Ql, rb, tid);
            load_tile64(sb + bo2 + T_KH, Kh, rb, tid);
            load_tile64(sb + bo2 + T_KL, Kl, rb, tid);
            load_tile64(sb + bo2 + T_VH, Vh, rb, tid);
            load_tile64(sb + bo2 + T_VL, Vl, rb, tid);
            CP_COMMIT();
        }
        __syncthreads();

        // ---- P1: S = Q K^T (fp32 frags), mask, rowsums, split to smem ----
        {
            float accS[2][2][4];
#pragma unroll
            for (int a = 0; a < 2; a++)
#pragma unroll
                for (int b = 0; b < 2; b++)
#pragma unroll
                    for (int e = 0; e < 4; e++) accS[a][b][e] = 0.f;
            mm64(sb + bo + T_QH, sb + bo + T_QL, sb + bo + T_KH, sb + bo + T_KL,
                 accS, wm, wn, lane);
#pragma unroll
            for (int mf = 0; mf < 2; mf++) {
                int r0 = wm * 32 + mf * 16 + (lane >> 2), r1 = r0 + 8;
                float rs0 = 0.f, rs1 = 0.f;
#pragma unroll
                for (int nf = 0; nf < 2; nf++) {
                    int cc = wn * 16 + nf * 8 + 2 * (lane & 3);
                    float a0 = (cc     <= r0) ? accS[mf][nf][0] : 0.f;
                    float a1 = (cc + 1 <= r0) ? accS[mf][nf][1] : 0.f;
                    float a2 = (cc     <= r1) ? accS[mf][nf][2] : 0.f;
                    float a3 = (cc + 1 <= r1) ? accS[mf][nf][3] : 0.f;
                    rs0 += a0 + a1; rs1 += a2 + a3;
                    unsigned short h0, l0, h1, l1;
                    split2u(a0, h0, l0); split2u(a1, h1, l1);
                    uint32_t so = SWZ64(r0, cc >> 3) + (cc & 7) * 2;
                    *(ushort2*)(smx + O_SH + so) = make_ushort2(h0, h1);
                    *(ushort2*)(smx + O_SL + so) = make_ushort2(l0, l1);
                    split2u(a2, h0, l0); split2u(a3, h1, l1);
                    so = SWZ64(r1, cc >> 3) + (cc & 7) * 2;
                    *(ushort2*)(smx + O_SH + so) = make_ushort2(h0, h1);
                    *(ushort2*)(smx + O_SL + so) = make_ushort2(l0, l1);
                }
                rs0 += __shfl_xor_sync(0xffffffffu, rs0, 1);
                rs0 += __shfl_xor_sync(0xffffffffu, rs0, 2);
                rs1 += __shfl_xor_sync(0xffffffffu, rs1, 1);
                rs1 += __shfl_xor_sync(0xffffffffu, rs1, 2);
                if ((lane & 3) == 0) {
                    denp[wn * 64 + r0] = rs0;
                    denp[wn * 64 + r1] = rs1;
                }
            }
        }
        __syncthreads();

        // ---- P2: den[i] = max(q_i.ks + rowsum, 1e-6) ----
        if (tid < 64) {
            int i = tid;
            float s = denp[i] + denp[64 + i] + denp[128 + i] + denp[192 + i];
            for (int d = 0; d < 64; d++) {
                uint32_t qo = SWZ64(i, d >> 3) + (d & 7) * 2;
                float qv = bfu(*(unsigned short*)(smx + bo + T_QH + qo)) +
                           bfu(*(unsigned short*)(smx + bo + T_QL + qo));
                s += qv * ksp[d];
            }
            denv[i] = fmaxf(s, 1e-6f);
        }
        __syncthreads();

        // ---- P3: O = Q.KVt + S.V ; /den ; split-store to gmem ----
        {
            float accO[2][2][4];
#pragma unroll
            for (int a = 0; a < 2; a++)
#pragma unroll
                for (int b = 0; b < 2; b++)
#pragma unroll
                    for (int e = 0; e < 4; e++) accO[a][b][e] = 0.f;
            mm64(sb + bo + T_QH, sb + bo + T_QL, sb + O_KVH, sb + O_KVL,
                 accO, wm, wn, lane);
            mm64(sb + O_SH, sb + O_SL, sb + O_VTH, sb + O_VTL,
                 accO, wm, wn, lane);
#pragma unroll
            for (int mf = 0; mf < 2; mf++) {
                int r0 = wm * 32 + mf * 16 + (lane >> 2), r1 = r0 + 8;
                float i0 = 1.f / denv[r0], i1 = 1.f / denv[r1];
#pragma unroll
                for (int nf = 0; nf < 2; nf++) {
                    int cc = wn * 16 + nf * 8 + 2 * (lane & 3);
                    unsigned short h0, l0, h1, l1;
                    size_t ro = (size_t)(bIdx * N_ + n0 + r0) * DIMM + hIdx * 64 + cc;
                    split2u(accO[mf][nf][0] * i0, h0, l0);
                    split2u(accO[mf][nf][1] * i0, h1, l1);
                    *(ushort2*)((unsigned short*)ah + ro) = make_ushort2(h0, h1);
                    *(ushort2*)((unsigned short*)al + ro) = make_ushort2(l0, l1);
                    ro = (size_t)(bIdx * N_ + n0 + r1) * DIMM + hIdx * 64 + cc;
                    split2u(accO[mf][nf][2] * i1, h0, l0);
                    split2u(accO[mf][nf][3] * i1, h1, l1);
                    *(ushort2*)((unsigned short*)ah + ro) = make_ushort2(h0, h1);
                    *(ushort2*)((unsigned short*)al + ro) = make_ushort2(l0, l1);
                }
            }
        }

        // ---- P4: KVt[m][d] += V^T K ; re-split mirror ; ks update ----
        {
            float accU[2][2][4];
#pragma unroll
            for (int a = 0; a < 2; a++)
#pragma unroll
                for (int b = 0; b < 2; b++)
#pragma unroll
                    for (int e = 0; e < 4; e++) accU[a][b][e] = 0.f;
            mm64(sb + O_VTH, sb + O_VTL, sb + O_KTH, sb + O_KTL,
                 accU, wm, wn, lane);
#pragma unroll
            for (int mf = 0; mf < 2; mf++) {
                int m0r = wm * 32 + mf * 16 + (lane >> 2), m1r = m0r + 8;
#pragma unroll
                for (int nf = 0; nf < 2; nf++) {
                    int dd = wn * 16 + nf * 8 + 2 * (lane & 3);
                    float* kvf = (float*)(smx + O_KVF);
                    kvf[m0r * 64 + dd]     += accU[mf][nf][0];
                    kvf[m0r * 64 + dd + 1] += accU[mf][nf][1];
                    kvf[m1r * 64 + dd]     += accU[mf][nf][2];
                    kvf[m1r * 64 + dd + 1] += accU[mf][nf][3];
                }
            }
        }
        __syncthreads();
        for (int idx = tid; idx < 4096; idx += 256) {
            int m = idx >> 6, d = idx & 63;
            float v = *(float*)(smx + O_KVF + idx * 4);
            unsigned short hh, ll;
            split2u(v, hh, ll);
            uint32_t o = SWZ64(m, d >> 3) + (d & 7) * 2;
            *(unsigned short*)(smx + O_KVH + o) = hh;
            *(unsigned short*)(smx + O_KVL + o) = ll;
        }
        if (tid < 64) {
            int d = tid;
            float s = ksp[d];
            for (int i2 = 0; i2 < 64; i2++) {
                uint32_t o = SWZ64(d, i2 >> 3) + (i2 & 7) * 2;
                s += bfu(*(unsigned short*)(smx + O_KTH + o)) +
                     bfu(*(unsigned short*)(smx + O_KTL + o));
            }
            ksp[d] = s;
        }
        __syncthreads();
    }
}

// ---------------- launch -----------------------------------------------------
extern "C" void kernel_launch(void* const* d_in, const int* in_sizes, int n_in,
                              void* d_out, int out_size) {
    const float* x    = (const float*)d_in[0];
    const float* wqkv = (const float*)d_in[1];
    const float* wout = (const float*)d_in[2];
    float* out = (float*)d_out;

    float* qkv;
    __nv_bfloat16 *Qh, *Ql, *Kh, *Kl, *Vh, *Vl;
    __nv_bfloat16 *xh, *xl, *ah, *al, *wqh, *wql, *woh, *wol;
    cudaGetSymbolAddress((void**)&qkv, g_qkv);
    cudaGetSymbolAddress((void**)&Qh,  g_Qh);
    cudaGetSymbolAddress((void**)&Ql,  g_Ql);
    cudaGetSymbolAddress((void**)&Kh,  g_Kh);
    cudaGetSymbolAddress((void**)&Kl,  g_Kl);
    cudaGetSymbolAddress((void**)&Vh,  g_Vh);
    cudaGetSymbolAddress((void**)&Vl,  g_Vl);
    cudaGetSymbolAddress((void**)&xh,  g_xh);
    cudaGetSymbolAddress((void**)&xl,  g_xl);
    cudaGetSymbolAddress((void**)&ah,  g_ah);
    cudaGetSymbolAddress((void**)&al,  g_al);
    cudaGetSymbolAddress((void**)&wqh, g_wqh);
    cudaGetSymbolAddress((void**)&wql, g_wql);
    cudaGetSymbolAddress((void**)&woh, g_woh);
    cudaGetSymbolAddress((void**)&wol, g_wol);

    cudaFuncSetAttribute(mma_gemm, cudaFuncAttributeMaxDynamicSharedMemorySize,
                         GEMM_SMEM);
    cudaFuncSetAttribute(linattn_mma, cudaFuncAttributeMaxDynamicSharedMemorySize,
                         LA_SMEM);

    // split x; transpose+split weights
    {
        int n4 = ROWS * DIMM / 4;
        split_bf16<<<(n4 + 255) / 256, 256>>>(x, xh, xl, n4);
        transpose_split<<<dim3(3 * DIMM / 32, DIMM / 32), dim3(32, 8)>>>(
            wqkv, wqh, wql, DIMM, 3 * DIMM);
        transpose_split<<<dim3(DIMM / 32, DIMM / 32), dim3(32, 8)>>>(
            wout, woh, wol, DIMM, DIMM);
    }
    // 1) qkv = x @ w_qkv   (tensor cores)
    mma_gemm<<<dim3(3 * DIMM / 128, ROWS / 128), 256, GEMM_SMEM>>>(
        xh, xl, wqh, wql, qkv, ROWS, 3 * DIMM, DIMM);
    // 2) RoPE + ELU -> bf16 hi/lo features
    {
        int total = B_ * N_ * HEADS * 32;
        rope_elu<<<(total + 255) / 256, 256>>>(qkv, Qh, Ql, Kh, Kl, Vh, Vl);
    }
    // 3) tensor-core chunked linear attention (emits bf16 hi/lo attn)
    linattn_mma<<<NBH, 256, LA_SMEM>>>(Qh, Ql, Kh, Kl, Vh, Vl, ah, al);
    // 4) out = attn @ w_out (tensor cores)
    mma_gemm<<<dim3(DIMM / 128, ROWS / 128), 256, GEMM_SMEM>>>(
        ah, al, woh, wol, out, ROWS, DIMM, DIMM);
}

// round 12
// speedup vs baseline: 1.4596x; 1.0909x over previous
#include <cuda_runtime.h>
#include <cuda_bf16.h>
#include <math.h>
#include <stdint.h>

#define B_   4
#define N_   4096
#define DIMM 1024
#define HEADS 16
#define HD   64
#define ROWS (B_*N_)          // 16384
#define NBH  (B_*HEADS)       // 64

// ---------------- scratch (device globals: allocation-free) ----------------
__device__ float g_qkv[(size_t)ROWS * 3 * DIMM];        // qkv fp32
__device__ __nv_bfloat16 g_Qh[(size_t)NBH * N_ * HD];   // featurized q/k/v bf16 splits
__device__ __nv_bfloat16 g_Ql[(size_t)NBH * N_ * HD];
__device__ __nv_bfloat16 g_Kh[(size_t)NBH * N_ * HD];
__device__ __nv_bfloat16 g_Kl[(size_t)NBH * N_ * HD];
__device__ __nv_bfloat16 g_Vh[(size_t)NBH * N_ * HD];
__device__ __nv_bfloat16 g_Vl[(size_t)NBH * N_ * HD];
__device__ __nv_bfloat16 g_xh [(size_t)ROWS * DIMM];    // x split
__device__ __nv_bfloat16 g_xl [(size_t)ROWS * DIMM];
__device__ __nv_bfloat16 g_ah [(size_t)ROWS * DIMM];    // attn split (linattn out)
__device__ __nv_bfloat16 g_al [(size_t)ROWS * DIMM];
__device__ __nv_bfloat16 g_wqh[(size_t)3 * DIMM * DIMM]; // wqkv^T split [N][K]
__device__ __nv_bfloat16 g_wql[(size_t)3 * DIMM * DIMM];
__device__ __nv_bfloat16 g_woh[(size_t)DIMM * DIMM];     // wout^T split
__device__ __nv_bfloat16 g_wol[(size_t)DIMM * DIMM];

// ---------------- helpers ----------------------------------------------------
__device__ __forceinline__ uint32_t smem_u32(const void* p) {
    uint32_t a;
    asm("{ .reg .u64 t; cvta.to.shared.u64 t, %1; cvt.u32.u64 %0, t; }"
        : "=r"(a) : "l"(p));
    return a;
}
__device__ __forceinline__ void cp16(uint32_t s, const void* g) {
    asm volatile("cp.async.cg.shared.global [%0], [%1], 16;" :: "r"(s), "l"(g));
}
#define CP_COMMIT() asm volatile("cp.async.commit_group;" ::: "memory")
#define CP_WAIT(n)  asm volatile("cp.async.wait_group %0;" :: "n"(n) : "memory")
#define LDSM4(r0, r1, r2, r3, addr) asm volatile( \
    "ldmatrix.sync.aligned.m8n8.x4.shared.b16 {%0,%1,%2,%3}, [%4];" \
    : "=r"(r0), "=r"(r1), "=r"(r2), "=r"(r3) : "r"(addr))
__device__ __forceinline__ void mma16816(float* c, const uint32_t* a,
                                         const uint32_t* b) {
    asm volatile(
        "mma.sync.aligned.m16n8k16.row.col.f32.bf16.bf16.f32 "
        "{%0,%1,%2,%3}, {%4,%5,%6,%7}, {%8,%9}, {%0,%1,%2,%3};"
        : "+f"(c[0]), "+f"(c[1]), "+f"(c[2]), "+f"(c[3])
        : "r"(a[0]), "r"(a[1]), "r"(a[2]), "r"(a[3]), "r"(b[0]), "r"(b[1]));
}
// 64B-row swizzle (GEMM stage tiles, V half tiles); ck in 0..3
__device__ __forceinline__ uint32_t swz(int r, int ck) {
    return (uint32_t)(((r >> 1) << 7) |
                      ((((((r & 1) << 2) | ck)) ^ ((r >> 1) & 7)) << 4));
}
// 128B-row swizzle (attention 64-col tiles); ck in 0..7
#define SWZ64(r, ck) ((uint32_t)((r) * 128 + ((((ck) ^ ((r) & 7))) << 4)))

__device__ __forceinline__ float bfu(unsigned short u) {
    return __bfloat162float(__ushort_as_bfloat16(u));
}
__device__ __forceinline__ void split2u(float v, unsigned short& hh,
                                        unsigned short& ll) {
    __nv_bfloat16 b = __float2bfloat16(v);
    hh = __bfloat16_as_ushort(b);
    ll = __bfloat16_as_ushort(__float2bfloat16(v - __bfloat162float(b)));
}

// ---------------- split fp32 -> bf16 hi/lo ----------------------------------
__global__ void split_bf16(const float* __restrict__ in,
                           __nv_bfloat16* __restrict__ hi,
                           __nv_bfloat16* __restrict__ lo, int n4) {
    int i = blockIdx.x * blockDim.x + threadIdx.x;
    if (i >= n4) return;
    float4 v = ((const float4*)in)[i];
    unsigned short h0, l0, h1, l1, h2, l2, h3, l3;
    split2u(v.x, h0, l0); split2u(v.y, h1, l1);
    split2u(v.z, h2, l2); split2u(v.w, h3, l3);
    ((ushort4*)hi)[i] = make_ushort4(h0, h1, h2, h3);
    ((ushort4*)lo)[i] = make_ushort4(l0, l1, l2, l3);
}

// ---------------- transpose + split: w[K][N] -> wt_hi/lo [N][K] --------------
__global__ void transpose_split(const float* __restrict__ w,
                                __nv_bfloat16* __restrict__ th,
                                __nv_bfloat16* __restrict__ tl, int K, int N) {
    __shared__ float t[32][33];
    int tx = threadIdx.x, ty = threadIdx.y;
    int x = blockIdx.x * 32 + tx;
#pragma unroll
    for (int j = 0; j < 32; j += 8) {
        int y = blockIdx.y * 32 + ty + j;
        t[ty + j][tx] = w[(size_t)y * N + x];
    }
    __syncthreads();
#pragma unroll
    for (int j = 0; j < 32; j += 8) {
        int n = blockIdx.x * 32 + ty + j;
        int k = blockIdx.y * 32 + tx;
        float v = t[tx][ty + j];
        __nv_bfloat16 h = __float2bfloat16(v);
        th[(size_t)n * K + k] = h;
        tl[(size_t)n * K + k] = __float2bfloat16(v - __bfloat162float(h));
    }
}

// ---------------- split-bf16 tensor-core GEMM (mma.sync) ---------------------
#define STAGE    32768
#define OFFS_AH  0
#define OFFS_AL  8192
#define OFFS_BH  16384
#define OFFS_BL  24576
#define GEMM_SMEM (2 * STAGE)

__global__ void __launch_bounds__(256, 2) mma_gemm(
    const __nv_bfloat16* __restrict__ Ah, const __nv_bfloat16* __restrict__ Al,
    const __nv_bfloat16* __restrict__ Bh, const __nv_bfloat16* __restrict__ Bl,
    float* __restrict__ C, int M, int N, int K) {
    extern __shared__ char sm[];
    const uint32_t sb = smem_u32(sm);
    const int tid = threadIdx.x;
    const int lane = tid & 31, wid = tid >> 5;
    const int warp_m = wid & 1, warp_n = wid >> 1;
    const int m0 = blockIdx.y * 128, n0 = blockIdx.x * 128;

    const int i0 = tid, i1 = tid + 256;
    const int lr0 = i0 >> 2, lc0 = i0 & 3;
    const int lr1 = i1 >> 2, lc1 = i1 & 3;
    const uint32_t so0 = swz(lr0, lc0), so1 = swz(lr1, lc1);

    uint32_t baseA[4], baseB[2];
#pragma unroll
    for (int mf = 0; mf < 4; mf++)
        baseA[mf] = swz(warp_m * 64 + mf * 16 + (lane & 15), lane >> 4);
#pragma unroll
    for (int p = 0; p < 2; p++)
        baseB[p] = swz(warp_n * 32 + p * 16 + ((lane >> 4) << 3) + (lane & 7),
                       (lane >> 3) & 1);

    float acc[4][4][4];
#pragma unroll
    for (int a = 0; a < 4; a++)
#pragma unroll
        for (int b = 0; b < 4; b++)
#pragma unroll
            for (int c = 0; c < 4; c++) acc[a][b][c] = 0.f;

    const int nIter = K >> 5;
    {
        uint32_t bs = sb;
        size_t a0 = (size_t)(m0 + lr0) * K + lc0 * 8;
        size_t a1 = (size_t)(m0 + lr1) * K + lc1 * 8;
        size_t b0 = (size_t)(n0 + lr0) * K + lc0 * 8;
        size_t b1 = (size_t)(n0 + lr1) * K + lc1 * 8;
        cp16(bs + OFFS_AH + so0, Ah + a0); cp16(bs + OFFS_AH + so1, Ah + a1);
        cp16(bs + OFFS_AL + so0, Al + a0); cp16(bs + OFFS_AL + so1, Al + a1);
        cp16(bs + OFFS_BH + so0, Bh + b0); cp16(bs + OFFS_BH + so1, Bh + b1);
        cp16(bs + OFFS_BL + so0, Bl + b0); cp16(bs + OFFS_BL + so1, Bl + b1);
        CP_COMMIT();
    }

    for (int it = 0; it < nIter; it++) {
        if (it + 1 < nIter) {
            int kk = (it + 1) << 5;
            uint32_t bs = sb + ((it + 1) & 1) * STAGE;
            size_t a0 = (size_t)(m0 + lr0) * K + kk + lc0 * 8;
            size_t a1 = (size_t)(m0 + lr1) * K + kk + lc1 * 8;
            size_t b0 = (size_t)(n0 + lr0) * K + kk + lc0 * 8;
            size_t b1 = (size_t)(n0 + lr1) * K + kk + lc1 * 8;
            cp16(bs + OFFS_AH + so0, Ah + a0); cp16(bs + OFFS_AH + so1, Ah + a1);
            cp16(bs + OFFS_AL + so0, Al + a0); cp16(bs + OFFS_AL + so1, Al + a1);
            cp16(bs + OFFS_BH + so0, Bh + b0); cp16(bs + OFFS_BH + so1, Bh + b1);
            cp16(bs + OFFS_BL + so0, Bl + b0); cp16(bs + OFFS_BL + so1, Bl + b1);
            CP_COMMIT();
            CP_WAIT(1);
        } else {
            CP_WAIT(0);
        }
        __syncthreads();

        const uint32_t ss = sb + (it & 1) * STAGE;
#pragma unroll
        for (int ks = 0; ks < 2; ks++) {
            const uint32_t kx = ks * 32;
            uint32_t bh[4][2], bl[4][2];
#pragma unroll
            for (int p = 0; p < 2; p++) {
                uint32_t r0, r1, r2, r3;
                LDSM4(r0, r1, r2, r3, ss + OFFS_BH + (baseB[p] ^ kx));
                bh[2 * p][0] = r0; bh[2 * p][1] = r1;
                bh[2 * p + 1][0] = r2; bh[2 * p + 1][1] = r3;
                LDSM4(r0, r1, r2, r3, ss + OFFS_BL + (baseB[p] ^ kx));
                bl[2 * p][0] = r0; bl[2 * p][1] = r1;
                bl[2 * p + 1][0] = r2; bl[2 * p + 1][1] = r3;
            }
#pragma unroll
            for (int mf = 0; mf < 4; mf++) {
                uint32_t ah[4], al[4];
                LDSM4(ah[0], ah[1], ah[2], ah[3], ss + OFFS_AH + (baseA[mf] ^ kx));
                LDSM4(al[0], al[1], al[2], al[3], ss + OFFS_AL + (baseA[mf] ^ kx));
#pragma unroll
                for (int nf = 0; nf < 4; nf++) {
                    mma16816(acc[mf][nf], ah, bh[nf]);
                    mma16816(acc[mf][nf], ah, bl[nf]);
                    mma16816(acc[mf][nf], al, bh[nf]);
                }
            }
        }
        __syncthreads();
    }

#pragma unroll
    for (int mf = 0; mf < 4; mf++) {
#pragma unroll
        for (int nf = 0; nf < 4; nf++) {
            int row = m0 + warp_m * 64 + mf * 16 + (lane >> 2);
            int col = n0 + warp_n * 32 + nf * 8 + 2 * (lane & 3);
            *(float2*)(C + (size_t)row * N + col) =
                make_float2(acc[mf][nf][0], acc[mf][nf][1]);
            *(float2*)(C + (size_t)(row + 8) * N + col) =
                make_float2(acc[mf][nf][2], acc[mf][nf][3]);
        }
    }
}

// ---------------- RoPE + ELU feature map -> bf16 hi/lo (B,H,N,D) ------------
__global__ void rope_elu(const float* __restrict__ qkv,
                         __nv_bfloat16* __restrict__ Qh, __nv_bfloat16* __restrict__ Ql,
                         __nv_bfloat16* __restrict__ Kh, __nv_bfloat16* __restrict__ Kl,
                         __nv_bfloat16* __restrict__ Vh, __nv_bfloat16* __restrict__ Vl) {
    int idx = blockIdx.x * blockDim.x + threadIdx.x;
    const int total = B_ * N_ * HEADS * 32;
    if (idx >= total) return;
    const int d2 = idx & 31;
    const int h  = (idx >> 5) & 15;
    const int n  = (idx >> 9) & 4095;
    const int b  = idx >> 21;

    size_t base = (size_t)(b * N_ + n) * (3 * DIMM);
    int c1 = h * 64 + d2;
    float q1 = qkv[base + c1],            q2 = qkv[base + c1 + 32];
    float k1 = qkv[base + 1024 + c1],     k2 = qkv[base + 1024 + c1 + 32];
    float v1 = qkv[base + 2048 + c1],     v2 = qkv[base + 2048 + c1 + 32];

    float inv = powf(10000.f, -(float)d2 * (1.f / 32.f));
    float ang = (float)n * inv;
    float cs = cosf(ang), sn = sinf(ang);
    float qr1 = q1 * cs - q2 * sn, qr2 = q1 * sn + q2 * cs;
    float kr1 = k1 * cs - k2 * sn, kr2 = k1 * sn + k2 * cs;

    const float SC = 0.35355339059327373f;
    float y;
    y = qr1 * SC; float fq1 = (y > 0.f) ? y + 1.f : expf(y);
    y = qr2 * SC; float fq2 = (y > 0.f) ? y + 1.f : expf(y);
    y = kr1 * SC; float fk1 = (y > 0.f) ? y + 1.f : expf(y);
    y = kr2 * SC; float fk2 = (y > 0.f) ? y + 1.f : expf(y);

    size_t ob = ((size_t)((b * HEADS + h)) * N_ + n) * HD;
    unsigned short hh, ll;
    split2u(fq1, hh, ll);
    ((unsigned short*)Qh)[ob + d2] = hh;      ((unsigned short*)Ql)[ob + d2] = ll;
    split2u(fq2, hh, ll);
    ((unsigned short*)Qh)[ob + d2 + 32] = hh; ((unsigned short*)Ql)[ob + d2 + 32] = ll;
    split2u(fk1, hh, ll);
    ((unsigned short*)Kh)[ob + d2] = hh;      ((unsigned short*)Kl)[ob + d2] = ll;
    split2u(fk2, hh, ll);
    ((unsigned short*)Kh)[ob + d2 + 32] = hh; ((unsigned short*)Kl)[ob + d2 + 32] = ll;
    split2u(v1, hh, ll);
    ((unsigned short*)Vh)[ob + d2] = hh;      ((unsigned short*)Vl)[ob + d2] = ll;
    split2u(v2, hh, ll);
    ((unsigned short*)Vh)[ob + d2 + 32] = hh; ((unsigned short*)Vl)[ob + d2 + 32] = ll;
}

// ---------------- mma-based chunked linear attention, m-split x2 -------------
// smem layout (bytes):
#define T_QH 0
#define T_QL 8192
#define T_KH 16384
#define T_KL 24576
#define T_VH 32768                 // 64x32 half tile (64B rows), 4096 B
#define T_VL 36864
#define BUFSZ 40960
#define O_KTH (2*BUFSZ)            // 81920  (64x64 SWZ64)
#define O_KTL (O_KTH + 8192)
#define O_VTH (O_KTL + 8192)       // 98304  (32x64 SWZ64, 4096 B)
#define O_VTL (O_VTH + 4096)
#define O_SH  (O_VTL + 4096)       // 106496 (64x64 SWZ64)
#define O_SL  (O_SH + 8192)
#define O_KVH (O_SL + 8192)        // 122880 (32x64 SWZ64, 4096 B)
#define O_KVL (O_KVH + 4096)
#define O_KVF (O_KVL + 4096)       // 131072 (fp32 32x64 = 8192 B)
#define O_KS  (O_KVF + 8192)       // 139264
#define O_DEN (O_KS + 256)
#define O_DENP (O_DEN + 256)
#define LA_SMEM (O_DENP + 1024)    // 140800

// 3-term 64x64x64 (full): per-warp 2mf x 2nf, warp grid 2x4.
__device__ __forceinline__ void mm64(uint32_t aHt, uint32_t aLt,
                                     uint32_t bHt, uint32_t bLt,
                                     float (*acc)[2][4], int wm, int wn, int lane) {
    const uint32_t aOff0 = SWZ64(wm * 32 + (lane & 15), (lane >> 4));
    const uint32_t aOff1 = SWZ64(wm * 32 + 16 + (lane & 15), (lane >> 4));
    const uint32_t bOff  = SWZ64(wn * 16 + ((lane >> 4) << 3) + (lane & 7),
                                 (lane >> 3) & 1);
#pragma unroll
    for (int kx = 0; kx < 4; kx++) {
        const uint32_t x = kx << 5;
        uint32_t BH[2][2], BL[2][2], r0, r1, r2, r3;
        LDSM4(r0, r1, r2, r3, bHt + (bOff ^ x));
        BH[0][0] = r0; BH[0][1] = r1; BH[1][0] = r2; BH[1][1] = r3;
        LDSM4(r0, r1, r2, r3, bLt + (bOff ^ x));
        BL[0][0] = r0; BL[0][1] = r1; BL[1][0] = r2; BL[1][1] = r3;
#pragma unroll
        for (int mf = 0; mf < 2; mf++) {
            uint32_t ao = (mf ? aOff1 : aOff0) ^ x;
            uint32_t AH[4], AL[4];
            LDSM4(AH[0], AH[1], AH[2], AH[3], aHt + ao);
            LDSM4(AL[0], AL[1], AL[2], AL[3], aLt + ao);
#pragma unroll
            for (int nf = 0; nf < 2; nf++) {
                mma16816(acc[mf][nf], AH, BH[nf]);
                mma16816(acc[mf][nf], AH, BL[nf]);
                mma16816(acc[mf][nf], AL, BH[nf]);
            }
        }
    }
}

// 3-term, one 16x16 output tile per warp at (ar, bc), k=64.
__device__ __forceinline__ void mm16(uint32_t aHt, uint32_t aLt,
                                     uint32_t bHt, uint32_t bLt,
                                     float (*acc)[4], int ar, int bc, int lane) {
    const uint32_t aOff = SWZ64(ar + (lane & 15), (lane >> 4));
    const uint32_t bOff = SWZ64(bc + ((lane >> 4) << 3) + (lane & 7),
                                (lane >> 3) & 1);
#pragma unroll
    for (int kx = 0; kx < 4; kx++) {
        const uint32_t x = kx << 5;
        uint32_t BH[2][2], BL[2][2], r0, r1, r2, r3;
        LDSM4(r0, r1, r2, r3, bHt + (bOff ^ x));
        BH[0][0] = r0; BH[0][1] = r1; BH[1][0] = r2; BH[1][1] = r3;
        LDSM4(r0, r1, r2, r3, bLt + (bOff ^ x));
        BL[0][0] = r0; BL[0][1] = r1; BL[1][0] = r2; BL[1][1] = r3;
        uint32_t AH[4], AL[4];
        LDSM4(AH[0], AH[1], AH[2], AH[3], aHt + (aOff ^ x));
        LDSM4(AL[0], AL[1], AL[2], AL[3], aLt + (aOff ^ x));
#pragma unroll
        for (int nf = 0; nf < 2; nf++) {
            mma16816(acc[nf], AH, BH[nf]);
            mma16816(acc[nf], AH, BL[nf]);
            mma16816(acc[nf], AL, BH[nf]);
        }
    }
}

__device__ __forceinline__ void load_tile64(uint32_t dst,
                                            const __nv_bfloat16* g,
                                            size_t rowbase, int tid) {
#pragma unroll
    for (int uu = 0; uu < 2; uu++) {
        int u = tid + uu * 256;
        int r = u >> 3, ck = u & 7;
        cp16(dst + SWZ64(r, ck), g + rowbase + r * 64 + ck * 8);
    }
}
__device__ __forceinline__ void load_vhalf(uint32_t dst,
                                           const __nv_bfloat16* g,
                                           size_t rowbase, int mh, int tid) {
    int r = tid >> 2, ck = tid & 3;
    cp16(dst + swz(r, ck), g + rowbase + r * 64 + mh * 32 + ck * 8);
}

__global__ void __launch_bounds__(256) linattn_mma(
    const __nv_bfloat16* __restrict__ Qh, const __nv_bfloat16* __restrict__ Ql,
    const __nv_bfloat16* __restrict__ Kh, const __nv_bfloat16* __restrict__ Kl,
    const __nv_bfloat16* __restrict__ Vh, const __nv_bfloat16* __restrict__ Vl,
    __nv_bfloat16* __restrict__ ah, __nv_bfloat16* __restrict__ al) {
    extern __shared__ __align__(128) char smx[];
    const uint32_t sb = smem_u32(smx);
    const int tid = threadIdx.x;
    const int lane = tid & 31, wid = tid >> 5;
    const int wm = wid & 1, wn = wid >> 1;          // P1 geometry (2x4)
    const int wr3 = (wid & 3) * 16, wc3 = (wid >> 2) * 16;  // P3: 64x32
    const int wr4 = (wid & 1) * 16, wc4 = (wid >> 1) * 16;  // P4: 32x64
    const int bh = blockIdx.x >> 1;
    const int mh = blockIdx.x & 1;
    const int bIdx = bh >> 4, hIdx = bh & 15;
    const size_t gb = (size_t)bh * N_ * HD;

    float* ksp  = (float*)(smx + O_KS);
    float* denp = (float*)(smx + O_DENP);
    float* denv = (float*)(smx + O_DEN);
    float* kvf  = (float*)(smx + O_KVF);

    // init state (32x64 half)
    for (int i = tid; i < 2048; i += 256) {
        kvf[i] = 0.f;
        *(unsigned short*)(smx + O_KVH + i * 2) = 0;
        *(unsigned short*)(smx + O_KVL + i * 2) = 0;
    }
    if (tid < 64) ksp[tid] = 0.f;

    // prefetch chunk 0
    load_tile64(sb + T_QH, Qh, gb, tid);
    load_tile64(sb + T_QL, Ql, gb, tid);
    load_tile64(sb + T_KH, Kh, gb, tid);
    load_tile64(sb + T_KL, Kl, gb, tid);
    load_vhalf(sb + T_VH, Vh, gb, mh, tid);
    load_vhalf(sb + T_VL, Vl, gb, mh, tid);
    CP_COMMIT();
    __syncthreads();

    for (int ch = 0; ch < 64; ch++) {
        const int n0 = ch * 64;
        const uint32_t bo = (ch & 1) * BUFSZ;
        CP_WAIT(0);
        __syncthreads();

        // build K^T (64x64) and V^T (32x64)
        for (int idx = tid; idx < 4096; idx += 256) {
            int i = idx >> 6, d = idx & 63;
            uint32_t ro = SWZ64(i, d >> 3) + (d & 7) * 2;
            uint32_t wo = SWZ64(d, i >> 3) + (i & 7) * 2;
            *(unsigned short*)(smx + O_KTH + wo) = *(unsigned short*)(smx + bo + T_KH + ro);
            *(unsigned short*)(smx + O_KTL + wo) = *(unsigned short*)(smx + bo + T_KL + ro);
        }
        for (int idx = tid; idx < 2048; idx += 256) {
            int m = idx >> 6, i = idx & 63;     // m local 0..31
            uint32_t ro = swz(i, m >> 3) + (m & 7) * 2;
            uint32_t wo = SWZ64(m, i >> 3) + (i & 7) * 2;
            *(unsigned short*)(smx + O_VTH + wo) = *(unsigned short*)(smx + bo + T_VH + ro);
            *(unsigned short*)(smx + O_VTL + wo) = *(unsigned short*)(smx + bo + T_VL + ro);
        }
        // prefetch next chunk
        if (ch + 1 < 64) {
            const uint32_t bo2 = ((ch + 1) & 1) * BUFSZ;
            size_t rb = gb + (size_t)(n0 + 64) * HD;
            load_tile64(sb + bo2 + T_QH, Qh, rb, tid);
            load_tile64(sb + bo2 + T_QL, Ql, rb, tid);
            load_tile64(sb + bo2 + T_KH, Kh, rb, tid);
            load_tile64(sb + bo2 + T_KL, Kl, rb, tid);
            load_vhalf(sb + bo2 + T_VH, Vh, rb, mh, tid);
            load_vhalf(sb + bo2 + T_VL, Vl, rb, mh, tid);
            CP_COMMIT();
        }
        __syncthreads();

        // ---- P1: S = Q K^T (fp32 frags), mask, rowsums, split to smem ----
        {
            float accS[2][2][4];
#pragma unroll
            for (int a = 0; a < 2; a++)
#pragma unroll
                for (int b = 0; b < 2; b++)
#pragma unroll
                    for (int e = 0; e < 4; e++) accS[a][b][e] = 0.f;
            mm64(sb + bo + T_QH, sb + bo + T_QL, sb + bo + T_KH, sb + bo + T_KL,
                 accS, wm, wn, lane);
#pragma unroll
            for (int mf = 0; mf < 2; mf++) {
                int r0 = wm * 32 + mf * 16 + (lane >> 2), r1 = r0 + 8;
                float rs0 = 0.f, rs1 = 0.f;
#pragma unroll
                for (int nf = 0; nf < 2; nf++) {
                    int cc = wn * 16 + nf * 8 + 2 * (lane & 3);
                    float a0 = (cc     <= r0) ? accS[mf][nf][0] : 0.f;
                    float a1 = (cc + 1 <= r0) ? accS[mf][nf][1] : 0.f;
                    float a2 = (cc     <= r1) ? accS[mf][nf][2] : 0.f;
                    float a3 = (cc + 1 <= r1) ? accS[mf][nf][3] : 0.f;
                    rs0 += a0 + a1; rs1 += a2 + a3;
                    unsigned short h0, l0, h1, l1;
                    split2u(a0, h0, l0); split2u(a1, h1, l1);
                    uint32_t so = SWZ64(r0, cc >> 3) + (cc & 7) * 2;
                    *(ushort2*)(smx + O_SH + so) = make_ushort2(h0, h1);
                    *(ushort2*)(smx + O_SL + so) = make_ushort2(l0, l1);
                    split2u(a2, h0, l0); split2u(a3, h1, l1);
                    so = SWZ64(r1, cc >> 3) + (cc & 7) * 2;
                    *(ushort2*)(smx + O_SH + so) = make_ushort2(h0, h1);
                    *(ushort2*)(smx + O_SL + so) = make_ushort2(l0, l1);
                }
                rs0 += __shfl_xor_sync(0xffffffffu, rs0, 1);
                rs0 += __shfl_xor_sync(0xffffffffu, rs0, 2);
                rs1 += __shfl_xor_sync(0xffffffffu, rs1, 1);
                rs1 += __shfl_xor_sync(0xffffffffu, rs1, 2);
                if ((lane & 3) == 0) {
                    denp[wn * 64 + r0] = rs0;
                    denp[wn * 64 + r1] = rs1;
                }
            }
        }
        __syncthreads();

        // ---- P2: den[i] = max(q_i.ks + rowsum, 1e-6) ----
        if (tid < 64) {
            int i = tid;
            float s = denp[i] + denp[64 + i] + denp[128 + i] + denp[192 + i];
            for (int d = 0; d < 64; d++) {
                uint32_t qo = SWZ64(i, d >> 3) + (d & 7) * 2;
                float qv = bfu(*(unsigned short*)(smx + bo + T_QH + qo)) +
                           bfu(*(unsigned short*)(smx + bo + T_QL + qo));
                s += qv * ksp[d];
            }
            denv[i] = fmaxf(s, 1e-6f);
        }
        __syncthreads();

        // ---- P3: O(64x32) = Q.KVt^T + S.Vt^T ; /den ; split-store ----
        {
            float accO[2][4];
#pragma unroll
            for (int b = 0; b < 2; b++)
#pragma unroll
                for (int e = 0; e < 4; e++) accO[b][e] = 0.f;
            mm16(sb + bo + T_QH, sb + bo + T_QL, sb + O_KVH, sb + O_KVL,
                 accO, wr3, wc3, lane);
            mm16(sb + O_SH, sb + O_SL, sb + O_VTH, sb + O_VTL,
                 accO, wr3, wc3, lane);
            int r0 = wr3 + (lane >> 2), r1 = r0 + 8;
            float i0 = 1.f / denv[r0], i1 = 1.f / denv[r1];
#pragma unroll
            for (int nf = 0; nf < 2; nf++) {
                int cc = wc3 + nf * 8 + 2 * (lane & 3);
                unsigned short h0, l0, h1, l1;
                size_t ro = (size_t)(bIdx * N_ + n0 + r0) * DIMM + hIdx * 64 +
                            mh * 32 + cc;
                split2u(accO[nf][0] * i0, h0, l0);
                split2u(accO[nf][1] * i0, h1, l1);
                *(ushort2*)((unsigned short*)ah + ro) = make_ushort2(h0, h1);
                *(ushort2*)((unsigned short*)al + ro) = make_ushort2(l0, l1);
                ro = (size_t)(bIdx * N_ + n0 + r1) * DIMM + hIdx * 64 +
                     mh * 32 + cc;
                split2u(accO[nf][2] * i1, h0, l0);
                split2u(accO[nf][3] * i1, h1, l1);
                *(ushort2*)((unsigned short*)ah + ro) = make_ushort2(h0, h1);
                *(ushort2*)((unsigned short*)al + ro) = make_ushort2(l0, l1);
            }
        }

        // ---- P4: KVt(32x64) += V^T K ----
        {
            float accU[2][4];
#pragma unroll
            for (int b = 0; b < 2; b++)
#pragma unroll
                for (int e = 0; e < 4; e++) accU[b][e] = 0.f;
            mm16(sb + O_VTH, sb + O_VTL, sb + O_KTH, sb + O_KTL,
                 accU, wr4, wc4, lane);
            int m0r = wr4 + (lane >> 2), m1r = m0r + 8;
#pragma unroll
            for (int nf = 0; nf < 2; nf++) {
                int dd = wc4 + nf * 8 + 2 * (lane & 3);
                kvf[m0r * 64 + dd]     += accU[nf][0];
                kvf[m0r * 64 + dd + 1] += accU[nf][1];
                kvf[m1r * 64 + dd]     += accU[nf][2];
                kvf[m1r * 64 + dd + 1] += accU[nf][3];
            }
        }
        __syncthreads();
        // re-split KV mirror (2048) + ks update
        for (int idx = tid; idx < 2048; idx += 256) {
            int m = idx >> 6, d = idx & 63;
            unsigned short hh, ll;
            split2u(kvf[idx], hh, ll);
            uint32_t o = SWZ64(m, d >> 3) + (d & 7) * 2;
            *(unsigned short*)(smx + O_KVH + o) = hh;
            *(unsigned short*)(smx + O_KVL + o) = ll;
        }
        if (tid < 64) {
            int d = tid;
            float s = ksp[d];
            for (int i2 = 0; i2 < 64; i2++) {
                uint32_t o = SWZ64(d, i2 >> 3) + (i2 & 7) * 2;
                s += bfu(*(unsigned short*)(smx + O_KTH + o)) +
                     bfu(*(unsigned short*)(smx + O_KTL + o));
            }
            ksp[d] = s;
        }
        __syncthreads();
    }
}

// ---------------- launch -----------------------------------------------------
extern "C" void kernel_launch(void* const* d_in, const int* in_sizes, int n_in,
                              void* d_out, int out_size) {
    const float* x    = (const float*)d_in[0];
    const float* wqkv = (const float*)d_in[1];
    const float* wout = (const float*)d_in[2];
    float* out = (float*)d_out;

    float* qkv;
    __nv_bfloat16 *Qh, *Ql, *Kh, *Kl, *Vh, *Vl;
    __nv_bfloat16 *xh, *xl, *ah, *al, *wqh, *wql, *woh, *wol;
    cudaGetSymbolAddress((void**)&qkv, g_qkv);
    cudaGetSymbolAddress((void**)&Qh,  g_Qh);
    cudaGetSymbolAddress((void**)&Ql,  g_Ql);
    cudaGetSymbolAddress((void**)&Kh,  g_Kh);
    cudaGetSymbolAddress((void**)&Kl,  g_Kl);
    cudaGetSymbolAddress((void**)&Vh,  g_Vh);
    cudaGetSymbolAddress((void**)&Vl,  g_Vl);
    cudaGetSymbolAddress((void**)&xh,  g_xh);
    cudaGetSymbolAddress((void**)&xl,  g_xl);
    cudaGetSymbolAddress((void**)&ah,  g_ah);
    cudaGetSymbolAddress((void**)&al,  g_al);
    cudaGetSymbolAddress((void**)&wqh, g_wqh);
    cudaGetSymbolAddress((void**)&wql, g_wql);
    cudaGetSymbolAddress((void**)&woh, g_woh);
    cudaGetSymbolAddress((void**)&wol, g_wol);

    cudaFuncSetAttribute(mma_gemm, cudaFuncAttributeMaxDynamicSharedMemorySize,
                         GEMM_SMEM);
    cudaFuncSetAttribute(linattn_mma, cudaFuncAttributeMaxDynamicSharedMemorySize,
                         LA_SMEM);

    // split x; transpose+split weights
    {
        int n4 = ROWS * DIMM / 4;
        split_bf16<<<(n4 + 255) / 256, 256>>>(x, xh, xl, n4);
        transpose_split<<<dim3(3 * DIMM / 32, DIMM / 32), dim3(32, 8)>>>(
            wqkv, wqh, wql, DIMM, 3 * DIMM);
        transpose_split<<<dim3(DIMM / 32, DIMM / 32), dim3(32, 8)>>>(
            wout, woh, wol, DIMM, DIMM);
    }
    // 1) qkv = x @ w_qkv   (tensor cores)
    mma_gemm<<<dim3(3 * DIMM / 128, ROWS / 128), 256, GEMM_SMEM>>>(
        xh, xl, wqh, wql, qkv, ROWS, 3 * DIMM, DIMM);
    // 2) RoPE + ELU -> bf16 hi/lo features
    {
        int total = B_ * N_ * HEADS * 32;
        rope_elu<<<(total + 255) / 256, 256>>>(qkv, Qh, Ql, Kh, Kl, Vh, Vl);
    }
    // 3) tensor-core chunked linear attention, m-split x2
    linattn_mma<<<NBH * 2, 256, LA_SMEM>>>(Qh, Ql, Kh, Kl, Vh, Vl, ah, al);
    // 4) out = attn @ w_out (tensor cores)
    mma_gemm<<<dim3(DIMM / 128, ROWS / 128), 256, GEMM_SMEM>>>(
        ah, al, woh, wol, out, ROWS, DIMM, DIMM);
}